// round 13
// baseline (speedup 1.0000x reference)
#include <cuda_runtime.h>
#include <cuda_bf16.h>
#include <cuda_fp16.h>
#include <cstdint>
#include <math.h>

// ---------------- constants ----------------
#define BB   16
#define NN   4096
#define DD   64
#define NPT  512
#define KK   32
#define P_TOT (BB*NPT*KK)     // 262144
#define PB   (128*NPT)        // 65536 per-batch (c,s) block
#define EPSF 1e-5f

// ---------------- scratch ----------------
__device__ __half g_hA[131L * P_TOT];           // 131 x P halves (rows 128..130 = rel_xyz)
__device__ __half g_hB[128L * P_TOT];           // 128 x P halves
__device__ float g_xp[BB*128*NPT];
__device__ float g_x0[BB*128*NPT];
__device__ float g_energy[BB*NPT*NPT];
__device__ float g_x2[BB*128*NPT];
__device__ float g_y[BB*128*NPT];
__device__ float g_pmax[128*BB*NPT];
__device__ float g_pmin[128*BB*NPT];
__device__ double g_ssum[5*128];
__device__ double g_ssq[5*128];
__device__ float g_colrcp[BB*NPT];
__device__ int   g_fps[BB*NPT];
__device__ int   g_nbr[BB*NPT*KK];

// ---------------- FPS (single barrier per iteration) ----------------
__global__ void __launch_bounds__(1024) fps_kernel(const float* __restrict__ xyz,
                                                   int* __restrict__ fps) {
    extern __shared__ char xsm[];
    float* sm = (float*)xsm;
    float* sx = sm;
    float* sy = sm + NN;
    float* sz = sm + 2*NN;
    __shared__ unsigned long long swarp[2][32];
    int b = blockIdx.x, tid = threadIdx.x;
    int lane = tid & 31, wid = tid >> 5;
    const float* base = xyz + (long)b*3*NN;
    for (int i = tid; i < NN; i += 1024) {
        sx[i] = base[i];
        sy[i] = base[NN + i];
        sz[i] = base[2*NN + i];
    }
    __syncthreads();
    float dist[4];
    dist[0] = dist[1] = dist[2] = dist[3] = 1e10f;
    int far = 0;
    for (int it = 0; it < NPT; ++it) {
        if (tid == 0) fps[b*NPT + it] = far;
        float cx = sx[far], cy = sy[far], cz = sz[far];
        unsigned long long best = 0ull;
        #pragma unroll
        for (int j = 0; j < 4; ++j) {
            int n = tid + j*1024;
            float dx = sx[n]-cx, dy = sy[n]-cy, dz = sz[n]-cz;
            float d = dx*dx + dy*dy + dz*dz;
            float dd = fminf(dist[j], d);
            dist[j] = dd;
            unsigned long long key =
                ((unsigned long long)__float_as_uint(dd) << 32) |
                (unsigned long long)(0xFFFFFFFFu - (unsigned)n);
            best = (key > best) ? key : best;
        }
        #pragma unroll
        for (int off = 16; off > 0; off >>= 1) {
            unsigned long long o = __shfl_xor_sync(0xFFFFFFFFu, best, off);
            best = (o > best) ? o : best;
        }
        if (lane == 0) swarp[it & 1][wid] = best;
        __syncthreads();
        best = swarp[it & 1][lane];
        #pragma unroll
        for (int off = 16; off > 0; off >>= 1) {
            unsigned long long o = __shfl_xor_sync(0xFFFFFFFFu, best, off);
            best = (o > best) ? o : best;
        }
        far = (int)(0xFFFFFFFFu - (unsigned)(best & 0xFFFFFFFFull));
    }
}

// ---------------- new_xyz output ----------------
__global__ void newxyz_kernel(float* __restrict__ out, const float* __restrict__ xyz,
                              const int* __restrict__ fps) {
    int i = blockIdx.x*256 + threadIdx.x;
    if (i >= BB*3*NPT) return;
    int s = i & 511;
    int c = (i >> 9) % 3;
    int b = i / (3*NPT);
    out[i] = xyz[(long)b*3*NN + c*NN + fps[b*NPT + s]];
}

// ---------------- ball query ----------------
__global__ void __launch_bounds__(256) ball_kernel(const float* __restrict__ xyz,
                                                   const int* __restrict__ fps,
                                                   int* __restrict__ nbr) {
    extern __shared__ char xsm[];
    float* sm = (float*)xsm;
    float* sx = sm;
    float* sy = sm + NN;
    float* sz = sm + 2*NN;
    __shared__ int snb[8][KK];
    int b = blockIdx.y, tid = threadIdx.x;
    const float* base = xyz + (long)b*3*NN;
    for (int i = tid; i < NN; i += 256) {
        sx[i] = base[i];
        sy[i] = base[NN + i];
        sz[i] = base[2*NN + i];
    }
    __syncthreads();
    int w = tid >> 5, lane = tid & 31;
    int s = blockIdx.x*8 + w;
    int fi = fps[b*NPT + s];
    float cx = sx[fi], cy = sy[fi], cz = sz[fi];
    float cn = cx*cx + cy*cy + cz*cz;
    const float R2 = (float)(0.4*0.4);
    int cnt = 0;
    for (int n0 = 0; n0 < NN && cnt < KK; n0 += 32) {
        int n = n0 + lane;
        float px = sx[n], py = sy[n], pz = sz[n];
        float pn = px*px + py*py + pz*pz;
        float dt = cx*px + cy*py + cz*pz;
        float sq = (cn + pn) - 2.0f*dt;
        bool in = !(sq > R2);
        unsigned m = __ballot_sync(0xFFFFFFFFu, in);
        int pos = cnt + __popc(m & ((1u << lane) - 1u));
        if (in && pos < KK) snb[w][pos] = n;
        cnt += __popc(m);
    }
    __syncwarp();
    int v = (lane < cnt) ? snb[w][lane] : snb[w][0];
    nbr[(b*NPT + s)*KK + lane] = v;
}

// ---------------- feature build (half output; also zeros BN stats) ----------------
__global__ void __launch_bounds__(256) feat_kernel(const float* __restrict__ points,
                                                   const float* __restrict__ xyz,
                                                   const int* __restrict__ fps,
                                                   const int* __restrict__ nbr,
                                                   __half* __restrict__ X0,
                                                   __half* __restrict__ relbuf) {
    int s = blockIdx.x, b = blockIdx.y, tid = threadIdx.x;
    if (s == 0 && b == 0) {
        for (int i = tid; i < 5*128; i += 256) { g_ssum[i] = 0.0; g_ssq[i] = 0.0; }
    }
    __shared__ int snb[KK];
    __shared__ float scen[DD];
    __shared__ float scxyz[3];
    int fi = fps[b*NPT + s];
    if (tid < KK) snb[tid] = nbr[(b*NPT + s)*KK + tid];
    if (tid >= 32 && tid < 32+DD) scen[tid-32] = points[(long)b*DD*NN + (tid-32)*NN + fi];
    if (tid >= 96 && tid < 99)   scxyz[tid-96] = xyz[(long)b*3*NN + (tid-96)*NN + fi];
    __syncthreads();
    int k = tid & 31, cb = tid >> 5;
    int n = snb[k];
    int base = (b*NPT + s)*KK + k;
    #pragma unroll
    for (int q = 0; q < 8; ++q) {
        int c = q*8 + cb;
        float v = points[(long)b*DD*NN + c*NN + n];
        X0[(long)c*P_TOT + base] = __float2half(v);
        X0[(long)(DD+c)*P_TOT + base] = __float2half(v - scen[c]);
    }
    if (cb < 3) {
        float v = xyz[(long)b*3*NN + cb*NN + n] - scxyz[cb];
        relbuf[(long)cb*P_TOT + base] = __float2half(v);
    }
}

// ---------------- mma helpers ----------------
__device__ __forceinline__ uint32_t f2tf32(float v) {
    uint32_t r;
    asm("cvt.rna.tf32.f32 %0, %1;" : "=r"(r) : "f"(v));
    return r;
}
__device__ __forceinline__ void mma_tf32(float* d, uint32_t a0, uint32_t a1,
                                         uint32_t a2, uint32_t a3,
                                         uint32_t b0, uint32_t b1) {
    asm volatile("mma.sync.aligned.m16n8k8.row.col.f32.tf32.tf32.f32 "
        "{%0,%1,%2,%3},{%4,%5,%6,%7},{%8,%9},{%0,%1,%2,%3};"
        : "+f"(d[0]), "+f"(d[1]), "+f"(d[2]), "+f"(d[3])
        : "r"(a0), "r"(a1), "r"(a2), "r"(a3), "r"(b0), "r"(b1));
}
__device__ __forceinline__ void mma_f16(float* d, uint32_t a0, uint32_t a1,
                                        uint32_t a2, uint32_t a3,
                                        uint32_t b0, uint32_t b1) {
    asm volatile("mma.sync.aligned.m16n8k16.row.col.f32.f16.f16.f32 "
        "{%0,%1,%2,%3},{%4,%5,%6,%7},{%8,%9},{%0,%1,%2,%3};"
        : "+f"(d[0]), "+f"(d[1]), "+f"(d[2]), "+f"(d[3])
        : "r"(a0), "r"(a1), "r"(a2), "r"(a3), "r"(b0), "r"(b1));
}
__device__ __forceinline__ void ldsm_x4_trans(uint32_t& r0, uint32_t& r1,
                                              uint32_t& r2, uint32_t& r3, uint32_t addr) {
    asm volatile("ldmatrix.sync.aligned.m8n8.x4.trans.shared.b16 {%0,%1,%2,%3}, [%4];"
        : "=r"(r0), "=r"(r1), "=r"(r2), "=r"(r3) : "r"(addr));
}

// ================= fp16 big-layer GEMM (double-buffered, 1 sync/chunk) =========
template<int COUT, bool XFORM, bool STATS, bool POOL>
__global__ void __launch_bounds__(256, (COUT == 64) ? 3 : 2)
gemm_h(const float* __restrict__ A, int lda,
       const __half* __restrict__ X,
       __half* __restrict__ Y,
       const float* __restrict__ bias,
       const double* __restrict__ bssum, const double* __restrict__ bssq,
       const float* __restrict__ bg, const float* __restrict__ bbe, int Cbn,
       double* __restrict__ ssum, double* __restrict__ ssq,
       float* __restrict__ pmax, float* __restrict__ pmin,
       int Cin)
{
    constexpr int MW = COUT / 4;
    constexpr int MF = MW / 16;
    constexpr int NH2 = COUT / 16;
    constexpr int XTILE = 32*128;
    constexpr int WTILE = COUT*40;
    extern __shared__ char xsm[];
    __half* sXh = (__half*)xsm;
    __half* sWh = sXh + 2*XTILE;
    __shared__ float tf_s[132], tf_h[132], tf_l[132];

    int p0 = blockIdx.x * 128;
    int tid = threadIdx.x;
    int lane = tid & 31, wid = tid >> 5;
    int warpM = wid >> 1, warpN = wid & 1;
    int gid = lane >> 2, tig = lane & 3;

    if (XFORM) {
        for (int c = tid; c < Cin; c += 256) {
            if (c < Cbn) {
                double m = bssum[c] / (double)P_TOT;
                double v = bssq[c] / (double)P_TOT - m*m;
                float sc = bg[c] * rsqrtf((float)v + EPSF);
                tf_s[c] = sc;
                tf_h[c] = bbe[c] - (float)m * sc;
                tf_l[c] = 0.f;
            } else {
                tf_s[c] = 1.f;
                tf_h[c] = 0.f;
                tf_l[c] = -3.4e38f;
            }
        }
    }

    uint32_t sX_base0 = (uint32_t)__cvta_generic_to_shared(sXh);

    float d[MF][8][4];
    #pragma unroll
    for (int mf = 0; mf < MF; ++mf)
        #pragma unroll
        for (int nf = 0; nf < 8; ++nf)
            #pragma unroll
            for (int i = 0; i < 4; ++i) d[mf][nf][i] = 0.f;

    uint4 xr[2];
    float wsf[2*NH2];
    int nchunk = (Cin + 31) >> 5;

    auto loadXreg = [&](int k0c) {
        #pragma unroll
        for (int j = 0; j < 2; ++j) {
            int id = tid + j*256;
            int k = id >> 4, seg = id & 15;
            int kg = k0c + k;
            uint4 v = make_uint4(0u, 0u, 0u, 0u);
            if (kg < Cin)
                v = *reinterpret_cast<const uint4*>(&X[(long)kg*P_TOT + p0 + seg*8]);
            xr[j] = v;
        }
    };
    auto storeX = [&](int k0c, int buf) {
        __half* dst = sXh + buf*XTILE;
        #pragma unroll
        for (int j = 0; j < 2; ++j) {
            int id = tid + j*256;
            int k = id >> 4, seg = id & 15;
            uint4 v = xr[j];
            if (XFORM) {
                int kg = k0c + k;
                if (kg < Cin) {
                    float s = tf_s[kg], h = tf_h[kg], l = tf_l[kg];
                    uint32_t* w = &v.x;
                    #pragma unroll
                    for (int q = 0; q < 4; ++q) {
                        __half2 hv = *reinterpret_cast<__half2*>(&w[q]);
                        float f0 = __low2float(hv), f1 = __high2float(hv);
                        f0 = fmaxf(fmaf(f0, s, h), l);
                        f1 = fmaxf(fmaf(f1, s, h), l);
                        __half2 ho = __floats2half2_rn(f0, f1);
                        w[q] = *reinterpret_cast<uint32_t*>(&ho);
                    }
                }
            }
            int segp = seg ^ (k & 7);
            *reinterpret_cast<uint4*>(&dst[k*128 + segp*8]) = v;
        }
    };
    auto loadWreg = [&](int k0c) {
        #pragma unroll
        for (int j = 0; j < NH2; ++j) {
            int hid = tid + j*256;
            int co = hid >> 4, kp = hid & 15;
            int k = k0c + 2*kp;
            wsf[2*j]   = (k   < Cin) ? A[(long)co*lda + k]   : 0.f;
            wsf[2*j+1] = (k+1 < Cin) ? A[(long)co*lda + k+1] : 0.f;
        }
    };
    auto storeW = [&](int buf) {
        __half* dst = sWh + buf*WTILE;
        #pragma unroll
        for (int j = 0; j < NH2; ++j) {
            int hid = tid + j*256;
            int co = hid >> 4, kp = hid & 15;
            __half2 hp = __floats2half2_rn(wsf[2*j], wsf[2*j+1]);
            *reinterpret_cast<__half2*>(&dst[co*40 + 2*kp]) = hp;
        }
    };

    auto mmaPhase = [&](int buf) {
        const __half* sW = sWh + buf*WTILE;
        uint32_t sX_base = sX_base0 + (uint32_t)(buf*XTILE*2);
        int mi = lane >> 3, lr = lane & 7;
        #pragma unroll
        for (int g16 = 0; g16 < 32; g16 += 16) {
            uint32_t a[MF][4];
            #pragma unroll
            for (int mf = 0; mf < MF; ++mf) {
                int r = warpM*MW + mf*16 + gid;
                a[mf][0] = *reinterpret_cast<const uint32_t*>(&sW[r*40 + g16 + 2*tig]);
                a[mf][1] = *reinterpret_cast<const uint32_t*>(&sW[(r+8)*40 + g16 + 2*tig]);
                a[mf][2] = *reinterpret_cast<const uint32_t*>(&sW[r*40 + g16 + 2*tig + 8]);
                a[mf][3] = *reinterpret_cast<const uint32_t*>(&sW[(r+8)*40 + g16 + 2*tig + 8]);
            }
            int kl = g16 + ((mi & 1) << 3) + lr;
            #pragma unroll
            for (int np = 0; np < 4; ++np) {
                int seg = warpN*8 + np*2 + (mi >> 1);
                int segp = seg ^ (kl & 7);
                uint32_t addr = sX_base + (uint32_t)((kl*128 + segp*8) * 2);
                uint32_t b0, b1, b2, b3;
                ldsm_x4_trans(b0, b1, b2, b3, addr);
                #pragma unroll
                for (int mf = 0; mf < MF; ++mf) {
                    mma_f16(d[mf][2*np],   a[mf][0], a[mf][1], a[mf][2], a[mf][3], b0, b1);
                    mma_f16(d[mf][2*np+1], a[mf][0], a[mf][1], a[mf][2], a[mf][3], b2, b3);
                }
            }
        }
    };

    loadXreg(0);
    loadWreg(0);
    if (XFORM) __syncthreads();
    storeX(0, 0);
    storeW(0);
    __syncthreads();
    for (int c0 = 0; c0 < nchunk; ++c0) {
        int cur = c0 & 1;
        if (c0 + 1 < nchunk) { loadXreg((c0+1)*32); loadWreg((c0+1)*32); }
        mmaPhase(cur);
        if (c0 + 1 < nchunk) {
            storeX((c0+1)*32, 1 - cur);
            storeW(1 - cur);
            __syncthreads();
        }
    }

    // epilogue
    #pragma unroll
    for (int mf = 0; mf < MF; ++mf) {
        int r = warpM*MW + mf*16 + gid;
        int co0 = r, co1 = r + 8;
        float bb0 = bias ? bias[co0] : 0.f;
        float bb1 = bias ? bias[co1] : 0.f;
        double s0 = 0.0, q0 = 0.0, s1 = 0.0, q1 = 0.0;
        float mxa[2], mna[2], mxb[2], mnb[2];
        if (POOL) {
            mxa[0] = mxa[1] = mxb[0] = mxb[1] = -3.4e38f;
            mna[0] = mna[1] = mnb[0] = mnb[1] =  3.4e38f;
        }
        #pragma unroll
        for (int nf = 0; nf < 8; ++nf) {
            int p = p0 + warpN*64 + nf*8 + 2*tig;
            float o0 = d[mf][nf][0] + bb0, o1 = d[mf][nf][1] + bb0;
            float o2 = d[mf][nf][2] + bb1, o3 = d[mf][nf][3] + bb1;
            if (!POOL) {
                *reinterpret_cast<__half2*>(&Y[(long)co0*P_TOT + p]) = __floats2half2_rn(o0, o1);
                *reinterpret_cast<__half2*>(&Y[(long)co1*P_TOT + p]) = __floats2half2_rn(o2, o3);
            } else {
                int g = nf >> 2;
                mxa[g] = fmaxf(mxa[g], fmaxf(o0, o1));
                mna[g] = fminf(mna[g], fminf(o0, o1));
                mxb[g] = fmaxf(mxb[g], fmaxf(o2, o3));
                mnb[g] = fminf(mnb[g], fminf(o2, o3));
            }
            if (STATS) {
                s0 += (double)o0 + (double)o1;
                q0 += (double)o0*o0 + (double)o1*o1;
                s1 += (double)o2 + (double)o3;
                q1 += (double)o2*o2 + (double)o3*o3;
            }
        }
        if (POOL) {
            const int PS = P_TOT >> 5;
            #pragma unroll
            for (int g = 0; g < 2; ++g) {
                float ma = mxa[g], na = mna[g], mb = mxb[g], nb = mnb[g];
                #pragma unroll
                for (int off = 1; off <= 2; off <<= 1) {
                    ma = fmaxf(ma, __shfl_xor_sync(0xFFFFFFFFu, ma, off));
                    na = fminf(na, __shfl_xor_sync(0xFFFFFFFFu, na, off));
                    mb = fmaxf(mb, __shfl_xor_sync(0xFFFFFFFFu, mb, off));
                    nb = fminf(nb, __shfl_xor_sync(0xFFFFFFFFu, nb, off));
                }
                if (tig == 0) {
                    int ps = (p0 >> 5) + warpN*2 + g;
                    pmax[(long)co0*PS + ps] = ma;
                    pmin[(long)co0*PS + ps] = na;
                    pmax[(long)co1*PS + ps] = mb;
                    pmin[(long)co1*PS + ps] = nb;
                }
            }
        }
        if (STATS) {
            #pragma unroll
            for (int off = 1; off <= 2; off <<= 1) {
                s0 += __shfl_xor_sync(0xFFFFFFFFu, s0, off);
                q0 += __shfl_xor_sync(0xFFFFFFFFu, q0, off);
                s1 += __shfl_xor_sync(0xFFFFFFFFu, s1, off);
                q1 += __shfl_xor_sync(0xFFFFFFFFu, q1, off);
            }
            if (tig == 0) {
                atomicAdd(&ssum[co0], s0);
                atomicAdd(&ssq[co0], q0);
                atomicAdd(&ssum[co1], s1);
                atomicAdd(&ssq[co1], q1);
            }
        }
    }
}

// ================= fp32/tf32 GEMM (attention; double-buffered, 1 sync/chunk) ===
template<int COUT, bool TRANSA, bool SUB, bool PSCALE, bool STATS>
__global__ void __launch_bounds__(256)
gemm_tc(const float* __restrict__ A, int lda, long aStride,
        const float* __restrict__ X, const float* __restrict__ X2, long xStride,
        const float* __restrict__ pscale, int psStride,
        float* __restrict__ Y, long yStride,
        const float* __restrict__ bias,
        double* __restrict__ ssum, double* __restrict__ ssq,
        int Cin, int P)
{
    constexpr int MW = COUT / 4;
    constexpr int MF = MW / 16;
    constexpr int NW = (COUT*32)/256;
    constexpr int XT = 32*136;
    constexpr int WT = COUT*36;
    extern __shared__ char xsm[];
    uint32_t* sXb = (uint32_t*)xsm;             // [2][32*136]
    uint32_t* sWb = sXb + 2*XT;                 // [2][COUT*36]

    int by = blockIdx.y;
    A += (long)by * aStride;
    X += (long)by * xStride;
    if (SUB) X2 += (long)by * xStride;
    Y += (long)by * yStride;
    int coBase = blockIdx.z * COUT;
    int p0 = blockIdx.x * 128;
    const float* psc = PSCALE ? (pscale + (long)by*psStride + p0) : nullptr;

    int tid = threadIdx.x;
    int lane = tid & 31, wid = tid >> 5;
    int warpM = wid >> 1, warpN = wid & 1;
    int gid = lane >> 2, tig = lane & 3;

    float d[MF][8][4];
    #pragma unroll
    for (int mf = 0; mf < MF; ++mf)
        #pragma unroll
        for (int nf = 0; nf < 8; ++nf)
            #pragma unroll
            for (int i = 0; i < 4; ++i) d[mf][nf][i] = 0.f;

    uint32_t xs[16];
    uint32_t ws[NW];
    int nchunk = (Cin + 31) >> 5;

    auto loadX_g = [&](int k0) {
        #pragma unroll
        for (int j = 0; j < 4; ++j) {
            int id = tid + j*256;
            int row = id >> 5, c4 = id & 31;
            int k = k0 + row;
            float4 v = make_float4(0.f, 0.f, 0.f, 0.f);
            if (k < Cin) {
                v = *reinterpret_cast<const float4*>(&X[(long)k*P + p0 + c4*4]);
                if (SUB) {
                    float4 u = *reinterpret_cast<const float4*>(&X2[(long)k*P + p0 + c4*4]);
                    v.x -= u.x; v.y -= u.y; v.z -= u.z; v.w -= u.w;
                }
                if (PSCALE) {
                    float4 pv = *reinterpret_cast<const float4*>(&psc[c4*4]);
                    v.x *= pv.x; v.y *= pv.y; v.z *= pv.z; v.w *= pv.w;
                }
            }
            xs[j*4+0] = f2tf32(v.x); xs[j*4+1] = f2tf32(v.y);
            xs[j*4+2] = f2tf32(v.z); xs[j*4+3] = f2tf32(v.w);
        }
    };
    auto loadW = [&](int k0) {
        #pragma unroll
        for (int j = 0; j < NW; ++j) {
            int id = tid + j*256;
            int co = id >> 5, kk = id & 31;
            int k = k0 + kk;
            float w = 0.f;
            if (k < Cin)
                w = TRANSA ? A[(long)k*lda + coBase + co]
                           : A[(long)(coBase + co)*lda + k];
            ws[j] = f2tf32(w);
        }
    };
    auto storeTiles = [&](int buf) {
        uint32_t* sX = sXb + buf*XT;
        uint32_t* sW = sWb + buf*WT;
        #pragma unroll
        for (int j = 0; j < 4; ++j) {
            int id = tid + j*256;
            int row = id >> 5, c4 = id & 31;
            *reinterpret_cast<uint4*>(sX + row*136 + c4*4) =
                make_uint4(xs[j*4], xs[j*4+1], xs[j*4+2], xs[j*4+3]);
        }
        #pragma unroll
        for (int j = 0; j < NW; ++j) {
            int id = tid + j*256;
            int co = id >> 5, kk = id & 31;
            sW[co*36 + kk] = ws[j];
        }
    };
    auto mmaPhase = [&](int buf) {
        const uint32_t* sX = sXb + buf*XT;
        const uint32_t* sW = sWb + buf*WT;
        #pragma unroll
        for (int k8 = 0; k8 < 4; ++k8) {
            int kb = k8*8;
            uint32_t a[MF][4];
            #pragma unroll
            for (int mf = 0; mf < MF; ++mf) {
                int r = warpM*MW + mf*16 + gid;
                a[mf][0] = sW[r*36 + kb + tig];
                a[mf][1] = sW[(r+8)*36 + kb + tig];
                a[mf][2] = sW[r*36 + kb + tig + 4];
                a[mf][3] = sW[(r+8)*36 + kb + tig + 4];
            }
            #pragma unroll
            for (int nf = 0; nf < 8; ++nf) {
                int col = warpN*64 + nf*8 + gid;
                uint32_t b0 = sX[(kb + tig)*136 + col];
                uint32_t b1 = sX[(kb + tig + 4)*136 + col];
                #pragma unroll
                for (int mf = 0; mf < MF; ++mf)
                    mma_tf32(d[mf][nf], a[mf][0], a[mf][1], a[mf][2], a[mf][3], b0, b1);
            }
        }
    };

    loadX_g(0);
    loadW(0);
    storeTiles(0);
    __syncthreads();
    for (int c0 = 0; c0 < nchunk; ++c0) {
        int cur = c0 & 1;
        if (c0 + 1 < nchunk) { loadX_g((c0+1)*32); loadW((c0+1)*32); }
        mmaPhase(cur);
        if (c0 + 1 < nchunk) {
            storeTiles(1 - cur);
            __syncthreads();
        }
    }

    #pragma unroll
    for (int mf = 0; mf < MF; ++mf) {
        int r = warpM*MW + mf*16 + gid;
        int co0 = coBase + r, co1 = co0 + 8;
        float bb0 = bias ? bias[co0] : 0.f;
        float bb1 = bias ? bias[co1] : 0.f;
        double s0 = 0.0, q0 = 0.0, s1 = 0.0, q1 = 0.0;
        #pragma unroll
        for (int nf = 0; nf < 8; ++nf) {
            int p = p0 + warpN*64 + nf*8 + 2*tig;
            float o0 = d[mf][nf][0] + bb0, o1 = d[mf][nf][1] + bb0;
            float o2 = d[mf][nf][2] + bb1, o3 = d[mf][nf][3] + bb1;
            *reinterpret_cast<float2*>(&Y[(long)co0*P + p]) = make_float2(o0, o1);
            *reinterpret_cast<float2*>(&Y[(long)co1*P + p]) = make_float2(o2, o3);
            if (STATS) {
                s0 += (double)o0 + (double)o1;
                q0 += (double)o0*o0 + (double)o1*o1;
                s1 += (double)o2 + (double)o3;
                q1 += (double)o2*o2 + (double)o3*o3;
            }
        }
        if (STATS) {
            #pragma unroll
            for (int off = 1; off <= 2; off <<= 1) {
                s0 += __shfl_xor_sync(0xFFFFFFFFu, s0, off);
                q0 += __shfl_xor_sync(0xFFFFFFFFu, q0, off);
                s1 += __shfl_xor_sync(0xFFFFFFFFu, s1, off);
                q1 += __shfl_xor_sync(0xFFFFFFFFu, q1, off);
            }
            if (tig == 0) {
                atomicAdd(&ssum[co0], s0);
                atomicAdd(&ssq[co0], q0);
                atomicAdd(&ssum[co1], s1);
                atomicAdd(&ssq[co1], q1);
            }
        }
    }
}

// ---------------- pooled BN+ReLU finalize (inline affine): xp[b][c][s] ----------------
__global__ void __launch_bounds__(256) pool_finalize(float* __restrict__ xp,
                              const float* __restrict__ pmax, const float* __restrict__ pmin,
                              const double* __restrict__ bssum, const double* __restrict__ bssq,
                              const float* __restrict__ bg, const float* __restrict__ bbe) {
    __shared__ float tf_s[128], tf_h[128];
    int tid = threadIdx.x;
    if (tid < 128) {
        double m = bssum[tid] / (double)P_TOT;
        double v = bssq[tid] / (double)P_TOT - m*m;
        float sc = bg[tid] * rsqrtf((float)v + EPSF);
        tf_s[tid] = sc;
        tf_h[tid] = bbe[tid] - (float)m * sc;
    }
    __syncthreads();
    int i = blockIdx.x*256 + tid;
    if (i >= BB*128*NPT) return;
    int s = i & 511, c = (i >> 9) & 127, b = i >> 16;
    int src = c*(BB*NPT) + b*NPT + s;
    float sc = tf_s[c], sh = tf_h[c];
    float v = (sc >= 0.f) ? pmax[src] : pmin[src];
    xp[i] = fmaxf(fmaf(v, sc, sh), 0.f);
}

// ---------------- softmax rows ----------------
__global__ void softmax_kernel(float* __restrict__ e) {
    int gw = (blockIdx.x*256 + threadIdx.x) >> 5;
    int lane = threadIdx.x & 31;
    if (gw >= BB*NPT) return;
    float* row = e + (long)gw * NPT;
    float v[16];
    float mx = -3.4e38f;
    #pragma unroll
    for (int i = 0; i < 16; ++i) { v[i] = row[lane + i*32]; mx = fmaxf(mx, v[i]); }
    #pragma unroll
    for (int off = 16; off > 0; off >>= 1)
        mx = fmaxf(mx, __shfl_xor_sync(0xFFFFFFFFu, mx, off));
    float sum = 0.f;
    #pragma unroll
    for (int i = 0; i < 16; ++i) { v[i] = expf(v[i] - mx); sum += v[i]; }
    #pragma unroll
    for (int off = 16; off > 0; off >>= 1)
        sum += __shfl_xor_sync(0xFFFFFFFFu, sum, off);
    #pragma unroll
    for (int i = 0; i < 16; ++i) row[lane + i*32] = v[i] / sum;
}

// ---------------- column sums (store reciprocal) ----------------
__global__ void colsum_kernel(const float* __restrict__ e, float* __restrict__ colrcp) {
    int b = blockIdx.x, m = blockIdx.y*128 + threadIdx.x;
    const float* E = e + (long)b * NPT * NPT;
    float s = 0.f;
    for (int n = 0; n < NPT; ++n) s += E[n*NPT + m];
    colrcp[b*NPT + m] = 1.f / (1e-9f + s);
}

// ---------------- final residual (inline bn1d affine) ----------------
__global__ void __launch_bounds__(256) final_kernel(float* __restrict__ out,
                             const float* __restrict__ xp,
                             const float* __restrict__ y,
                             const double* __restrict__ bssum, const double* __restrict__ bssq,
                             const float* __restrict__ bg, const float* __restrict__ bbe,
                             const float* __restrict__ alpha, const float* __restrict__ beta) {
    __shared__ float tf_s[128], tf_h[128];
    int tid = threadIdx.x;
    if (tid < 128) {
        double m = bssum[tid] / (double)(BB*NPT);
        double v = bssq[tid] / (double)(BB*NPT) - m*m;
        float sc = bg[tid] * rsqrtf((float)v + EPSF);
        tf_s[tid] = sc;
        tf_h[tid] = bbe[tid] - (float)m * sc;
    }
    __syncthreads();
    int i = blockIdx.x*256 + tid;
    if (i >= BB*128*NPT) return;
    int c = (i >> 9) & 127;
    float xr = fmaxf(fmaf(y[i], tf_s[c], tf_h[c]), 0.f);
    out[i] = xp[i] + alpha[c]*xr + beta[c];
}

// ---------------- launch ----------------
extern "C" void kernel_launch(void* const* d_in, const int* in_sizes, int n_in,
                              void* d_out, int out_size) {
    const float* xyz    = (const float*)d_in[0];
    const float* points = (const float*)d_in[1];
    const float* w0 = (const float*)d_in[2];
    const float* b0 = (const float*)d_in[3];
    const float* g0 = (const float*)d_in[4];
    const float* be0= (const float*)d_in[5];
    const float* w1 = (const float*)d_in[6];
    const float* b1 = (const float*)d_in[7];
    const float* g1 = (const float*)d_in[8];
    const float* be1= (const float*)d_in[9];
    const float* w2 = (const float*)d_in[10];
    const float* b2 = (const float*)d_in[11];
    const float* g2 = (const float*)d_in[12];
    const float* be2= (const float*)d_in[13];
    const float* wl = (const float*)d_in[14];
    const float* bl = (const float*)d_in[15];
    const float* gl = (const float*)d_in[16];
    const float* bel= (const float*)d_in[17];
    const float* wv = (const float*)d_in[18];
    const float* bv = (const float*)d_in[19];
    const float* wt = (const float*)d_in[20];
    const float* bt = (const float*)d_in[21];
    const float* gn = (const float*)d_in[22];
    const float* gb = (const float*)d_in[23];
    const float* alpha = (const float*)d_in[24];
    const float* beta  = (const float*)d_in[25];
    float* out = (float*)d_out;

    float *xp, *x0, *energy, *x2, *y, *colrcp, *pmax, *pmin;
    __half *hA, *hB;
    double *ssum, *ssq;
    int *fps, *nbr;
    cudaGetSymbolAddress((void**)&hA, g_hA);
    cudaGetSymbolAddress((void**)&hB, g_hB);
    cudaGetSymbolAddress((void**)&xp, g_xp);
    cudaGetSymbolAddress((void**)&x0, g_x0);
    cudaGetSymbolAddress((void**)&energy, g_energy);
    cudaGetSymbolAddress((void**)&x2, g_x2);
    cudaGetSymbolAddress((void**)&y, g_y);
    cudaGetSymbolAddress((void**)&ssum, g_ssum);
    cudaGetSymbolAddress((void**)&ssq, g_ssq);
    cudaGetSymbolAddress((void**)&colrcp, g_colrcp);
    cudaGetSymbolAddress((void**)&pmax, g_pmax);
    cudaGetSymbolAddress((void**)&pmin, g_pmin);
    cudaGetSymbolAddress((void**)&fps, g_fps);
    cudaGetSymbolAddress((void**)&nbr, g_nbr);

    const int SMEM_PTS = 3*NN*sizeof(float);   // 48KB
    cudaFuncSetAttribute(fps_kernel,  cudaFuncAttributeMaxDynamicSharedMemorySize, 64*1024);
    cudaFuncSetAttribute(ball_kernel, cudaFuncAttributeMaxDynamicSharedMemorySize, 64*1024);

    const int SM_H64  = 2*(32*128 + 64*40) * 2;       // 26624
    const int SM_H128 = 2*(32*128 + 128*40) * 2;      // 36864
    const int SM_T128 = 2*(32*136 + 128*36) * 4;      // 71680
    const int SM_T64  = 2*(32*136 + 64*36) * 4;       // 53248
    cudaFuncSetAttribute(gemm_tc<128,true,false,false,false>,
                         cudaFuncAttributeMaxDynamicSharedMemorySize, SM_T128);
    cudaFuncSetAttribute(gemm_tc<64,false,false,false,false>,
                         cudaFuncAttributeMaxDynamicSharedMemorySize, SM_T64);
    cudaFuncSetAttribute(gemm_tc<64,false,false,true,false>,
                         cudaFuncAttributeMaxDynamicSharedMemorySize, SM_T64);
    cudaFuncSetAttribute(gemm_tc<64,false,true,false,true>,
                         cudaFuncAttributeMaxDynamicSharedMemorySize, SM_T64);

    // geometry (4th launch = L0 fp16 GEMM for ncu capture)
    fps_kernel<<<BB, 1024, SMEM_PTS>>>(xyz, fps);
    ball_kernel<<<dim3(NPT/8, BB), 256, SMEM_PTS>>>(xyz, fps, nbr);
    feat_kernel<<<dim3(NPT, BB), 256>>>(points, xyz, fps, nbr, hB, hA + 128L*P_TOT);

    // L0: 128->64, stats slot0
    gemm_h<64,false,true,false><<<P_TOT/128, 256, SM_H64>>>(
        w0, 128, hB, hA, b0, nullptr, nullptr, nullptr, nullptr, 0,
        ssum+0, ssq+0, nullptr, nullptr, 128);
    newxyz_kernel<<<(BB*3*NPT + 255)/256, 256>>>(out, xyz, fps);

    // L1: 64->64, xform from slot0 stats (g0/be0), stats slot1
    gemm_h<64,true,true,false><<<P_TOT/128, 256, SM_H64>>>(
        w1, 64, hA, hB, b1, ssum+0, ssq+0, g0, be0, 64,
        ssum+128, ssq+128, nullptr, nullptr, 64);

    // L2: 64->128, xform from slot1 (g1/be1), stats slot2
    gemm_h<128,true,true,false><<<P_TOT/128, 256, SM_H128>>>(
        w2, 64, hB, hA, b2, ssum+128, ssq+128, g1, be1, 64,
        ssum+256, ssq+256, nullptr, nullptr, 64);

    // Ll: 131->128, xform from slot2 (g2/be2, 128 BN + 3 pass), stats slot3, POOL
    gemm_h<128,true,true,true><<<P_TOT/128, 256, SM_H128>>>(
        wl, 131, hA, nullptr, bl, ssum+256, ssq+256, g2, be2, 128,
        ssum+384, ssq+384, pmax, pmin, 131);
    pool_finalize<<<(BB*128*NPT + 255)/256, 256>>>(xp, pmax, pmin,
        ssum+384, ssq+384, gl, bel);

    // attention (tf32, double-buffered); wv/x2/wt split into COUT=64 tiles
    gemm_tc<64,false,false,false,false><<<dim3(NPT/128, BB, 2), 256, SM_T64>>>(
        wv, 128, 0, xp, nullptr, PB, nullptr, 0, x0, PB, bv,
        nullptr, nullptr, 128, NPT);
    gemm_tc<128,true,false,false,false><<<dim3(NPT/128, BB, 4), 256, SM_T128>>>(
        xp, NPT, PB, x0, nullptr, PB, nullptr, 0, energy, (long)NPT*NPT, nullptr,
        nullptr, nullptr, 128, NPT);
    softmax_kernel<<<(BB*NPT*32 + 255)/256, 256>>>(energy);
    colsum_kernel<<<dim3(BB, NPT/128), 128>>>(energy, colrcp);
    gemm_tc<64,false,false,true,false><<<dim3(NPT/128, BB, 2), 256, SM_T64>>>(
        x0, NPT, PB, energy, nullptr, (long)NPT*NPT, colrcp, NPT, x2, PB, nullptr,
        nullptr, nullptr, NPT, NPT);
    gemm_tc<64,false,true,false,true><<<dim3(NPT/128, BB, 2), 256, SM_T64>>>(
        wt, 128, 0, xp, x2, PB, nullptr, 0, y, PB, bt,
        ssum+512, ssq+512, 128, NPT);

    final_kernel<<<(BB*128*NPT + 255)/256, 256>>>(out + BB*3*NPT, xp, y,
        ssum+512, ssq+512, gn, gb, alpha, beta);
}

// round 14
// speedup vs baseline: 1.0146x; 1.0146x over previous
#include <cuda_runtime.h>
#include <cuda_bf16.h>
#include <cuda_fp16.h>
#include <cstdint>
#include <math.h>

// ---------------- constants ----------------
#define BB   16
#define NN   4096
#define DD   64
#define NPT  512
#define KK   32
#define P_TOT (BB*NPT*KK)     // 262144
#define PB   (128*NPT)        // 65536 per-batch (c,s) block
#define EPSF 1e-5f

// ---------------- scratch ----------------
__device__ __half g_hA[131L * P_TOT];           // 131 x P halves (rows 128..130 = rel_xyz)
__device__ __half g_hB[128L * P_TOT];           // 128 x P halves
__device__ float g_xp[BB*128*NPT];
__device__ float g_x0[BB*128*NPT];
__device__ float g_energy[BB*NPT*NPT];
__device__ float g_x2[BB*128*NPT];
__device__ float g_y[BB*128*NPT];
__device__ float g_pmax[128*BB*NPT];
__device__ float g_pmin[128*BB*NPT];
__device__ double g_ssum[5*128];
__device__ double g_ssq[5*128];
__device__ float g_colrcp[BB*NPT];
__device__ int   g_fps[BB*NPT];
__device__ int   g_nbr[BB*NPT*KK];

// ---------------- FPS (single barrier per iteration) ----------------
__global__ void __launch_bounds__(1024) fps_kernel(const float* __restrict__ xyz,
                                                   int* __restrict__ fps) {
    extern __shared__ char xsm[];
    float* sm = (float*)xsm;
    float* sx = sm;
    float* sy = sm + NN;
    float* sz = sm + 2*NN;
    __shared__ unsigned long long swarp[2][32];
    int b = blockIdx.x, tid = threadIdx.x;
    int lane = tid & 31, wid = tid >> 5;
    const float* base = xyz + (long)b*3*NN;
    for (int i = tid; i < NN; i += 1024) {
        sx[i] = base[i];
        sy[i] = base[NN + i];
        sz[i] = base[2*NN + i];
    }
    __syncthreads();
    float dist[4];
    dist[0] = dist[1] = dist[2] = dist[3] = 1e10f;
    int far = 0;
    for (int it = 0; it < NPT; ++it) {
        if (tid == 0) fps[b*NPT + it] = far;
        float cx = sx[far], cy = sy[far], cz = sz[far];
        unsigned long long best = 0ull;
        #pragma unroll
        for (int j = 0; j < 4; ++j) {
            int n = tid + j*1024;
            float dx = sx[n]-cx, dy = sy[n]-cy, dz = sz[n]-cz;
            float d = dx*dx + dy*dy + dz*dz;
            float dd = fminf(dist[j], d);
            dist[j] = dd;
            unsigned long long key =
                ((unsigned long long)__float_as_uint(dd) << 32) |
                (unsigned long long)(0xFFFFFFFFu - (unsigned)n);
            best = (key > best) ? key : best;
        }
        #pragma unroll
        for (int off = 16; off > 0; off >>= 1) {
            unsigned long long o = __shfl_xor_sync(0xFFFFFFFFu, best, off);
            best = (o > best) ? o : best;
        }
        if (lane == 0) swarp[it & 1][wid] = best;
        __syncthreads();
        best = swarp[it & 1][lane];
        #pragma unroll
        for (int off = 16; off > 0; off >>= 1) {
            unsigned long long o = __shfl_xor_sync(0xFFFFFFFFu, best, off);
            best = (o > best) ? o : best;
        }
        far = (int)(0xFFFFFFFFu - (unsigned)(best & 0xFFFFFFFFull));
    }
}

// ---------------- new_xyz output ----------------
__global__ void newxyz_kernel(float* __restrict__ out, const float* __restrict__ xyz,
                              const int* __restrict__ fps) {
    int i = blockIdx.x*256 + threadIdx.x;
    if (i >= BB*3*NPT) return;
    int s = i & 511;
    int c = (i >> 9) % 3;
    int b = i / (3*NPT);
    out[i] = xyz[(long)b*3*NN + c*NN + fps[b*NPT + s]];
}

// ---------------- ball query ----------------
__global__ void __launch_bounds__(256) ball_kernel(const float* __restrict__ xyz,
                                                   const int* __restrict__ fps,
                                                   int* __restrict__ nbr) {
    extern __shared__ char xsm[];
    float* sm = (float*)xsm;
    float* sx = sm;
    float* sy = sm + NN;
    float* sz = sm + 2*NN;
    __shared__ int snb[8][KK];
    int b = blockIdx.y, tid = threadIdx.x;
    const float* base = xyz + (long)b*3*NN;
    for (int i = tid; i < NN; i += 256) {
        sx[i] = base[i];
        sy[i] = base[NN + i];
        sz[i] = base[2*NN + i];
    }
    __syncthreads();
    int w = tid >> 5, lane = tid & 31;
    int s = blockIdx.x*8 + w;
    int fi = fps[b*NPT + s];
    float cx = sx[fi], cy = sy[fi], cz = sz[fi];
    float cn = cx*cx + cy*cy + cz*cz;
    const float R2 = (float)(0.4*0.4);
    int cnt = 0;
    for (int n0 = 0; n0 < NN && cnt < KK; n0 += 32) {
        int n = n0 + lane;
        float px = sx[n], py = sy[n], pz = sz[n];
        float pn = px*px + py*py + pz*pz;
        float dt = cx*px + cy*py + cz*pz;
        float sq = (cn + pn) - 2.0f*dt;
        bool in = !(sq > R2);
        unsigned m = __ballot_sync(0xFFFFFFFFu, in);
        int pos = cnt + __popc(m & ((1u << lane) - 1u));
        if (in && pos < KK) snb[w][pos] = n;
        cnt += __popc(m);
    }
    __syncwarp();
    int v = (lane < cnt) ? snb[w][lane] : snb[w][0];
    nbr[(b*NPT + s)*KK + lane] = v;
}

// ---------------- feature build (half output; also zeros BN stats) ----------------
__global__ void __launch_bounds__(256) feat_kernel(const float* __restrict__ points,
                                                   const float* __restrict__ xyz,
                                                   const int* __restrict__ fps,
                                                   const int* __restrict__ nbr,
                                                   __half* __restrict__ X0,
                                                   __half* __restrict__ relbuf) {
    int s = blockIdx.x, b = blockIdx.y, tid = threadIdx.x;
    if (s == 0 && b == 0) {
        for (int i = tid; i < 5*128; i += 256) { g_ssum[i] = 0.0; g_ssq[i] = 0.0; }
    }
    __shared__ int snb[KK];
    __shared__ float scen[DD];
    __shared__ float scxyz[3];
    int fi = fps[b*NPT + s];
    if (tid < KK) snb[tid] = nbr[(b*NPT + s)*KK + tid];
    if (tid >= 32 && tid < 32+DD) scen[tid-32] = points[(long)b*DD*NN + (tid-32)*NN + fi];
    if (tid >= 96 && tid < 99)   scxyz[tid-96] = xyz[(long)b*3*NN + (tid-96)*NN + fi];
    __syncthreads();
    int k = tid & 31, cb = tid >> 5;
    int n = snb[k];
    int base = (b*NPT + s)*KK + k;
    #pragma unroll
    for (int q = 0; q < 8; ++q) {
        int c = q*8 + cb;
        float v = points[(long)b*DD*NN + c*NN + n];
        X0[(long)c*P_TOT + base] = __float2half(v);
        X0[(long)(DD+c)*P_TOT + base] = __float2half(v - scen[c]);
    }
    if (cb < 3) {
        float v = xyz[(long)b*3*NN + cb*NN + n] - scxyz[cb];
        relbuf[(long)cb*P_TOT + base] = __float2half(v);
    }
}

// ---------------- mma helpers ----------------
__device__ __forceinline__ uint32_t f2tf32(float v) {
    uint32_t r;
    asm("cvt.rna.tf32.f32 %0, %1;" : "=r"(r) : "f"(v));
    return r;
}
__device__ __forceinline__ void mma_tf32(float* d, uint32_t a0, uint32_t a1,
                                         uint32_t a2, uint32_t a3,
                                         uint32_t b0, uint32_t b1) {
    asm volatile("mma.sync.aligned.m16n8k8.row.col.f32.tf32.tf32.f32 "
        "{%0,%1,%2,%3},{%4,%5,%6,%7},{%8,%9},{%0,%1,%2,%3};"
        : "+f"(d[0]), "+f"(d[1]), "+f"(d[2]), "+f"(d[3])
        : "r"(a0), "r"(a1), "r"(a2), "r"(a3), "r"(b0), "r"(b1));
}
__device__ __forceinline__ void mma_f16(float* d, uint32_t a0, uint32_t a1,
                                        uint32_t a2, uint32_t a3,
                                        uint32_t b0, uint32_t b1) {
    asm volatile("mma.sync.aligned.m16n8k16.row.col.f32.f16.f16.f32 "
        "{%0,%1,%2,%3},{%4,%5,%6,%7},{%8,%9},{%0,%1,%2,%3};"
        : "+f"(d[0]), "+f"(d[1]), "+f"(d[2]), "+f"(d[3])
        : "r"(a0), "r"(a1), "r"(a2), "r"(a3), "r"(b0), "r"(b1));
}
__device__ __forceinline__ void ldsm_x4_trans(uint32_t& r0, uint32_t& r1,
                                              uint32_t& r2, uint32_t& r3, uint32_t addr) {
    asm volatile("ldmatrix.sync.aligned.m8n8.x4.trans.shared.b16 {%0,%1,%2,%3}, [%4];"
        : "=r"(r0), "=r"(r1), "=r"(r2), "=r"(r3) : "r"(addr));
}

// ================= fp16 big-layer GEMM (double-buffered, 1 sync/chunk) =========
template<int COUT, bool XFORM, bool STATS, bool POOL>
__global__ void __launch_bounds__(256, (COUT == 64) ? 3 : 2)
gemm_h(const float* __restrict__ A, int lda,
       const __half* __restrict__ X,
       __half* __restrict__ Y,
       const float* __restrict__ bias,
       const double* __restrict__ bssum, const double* __restrict__ bssq,
       const float* __restrict__ bg, const float* __restrict__ bbe, int Cbn,
       double* __restrict__ ssum, double* __restrict__ ssq,
       float* __restrict__ pmax, float* __restrict__ pmin,
       int Cin)
{
    constexpr int MW = COUT / 4;
    constexpr int MF = MW / 16;
    constexpr int NH2 = COUT / 16;
    constexpr int XTILE = 32*128;
    constexpr int WTILE = COUT*40;
    extern __shared__ char xsm[];
    __half* sXh = (__half*)xsm;
    __half* sWh = sXh + 2*XTILE;
    __shared__ float tf_s[132], tf_h[132], tf_l[132];

    int p0 = blockIdx.x * 128;
    int tid = threadIdx.x;
    int lane = tid & 31, wid = tid >> 5;
    int warpM = wid >> 1, warpN = wid & 1;
    int gid = lane >> 2, tig = lane & 3;

    if (XFORM) {
        for (int c = tid; c < Cin; c += 256) {
            if (c < Cbn) {
                double m = bssum[c] / (double)P_TOT;
                double v = bssq[c] / (double)P_TOT - m*m;
                float sc = bg[c] * rsqrtf((float)v + EPSF);
                tf_s[c] = sc;
                tf_h[c] = bbe[c] - (float)m * sc;
                tf_l[c] = 0.f;
            } else {
                tf_s[c] = 1.f;
                tf_h[c] = 0.f;
                tf_l[c] = -3.4e38f;
            }
        }
    }

    uint32_t sX_base0 = (uint32_t)__cvta_generic_to_shared(sXh);

    float d[MF][8][4];
    #pragma unroll
    for (int mf = 0; mf < MF; ++mf)
        #pragma unroll
        for (int nf = 0; nf < 8; ++nf)
            #pragma unroll
            for (int i = 0; i < 4; ++i) d[mf][nf][i] = 0.f;

    uint4 xr[2];
    float wsf[2*NH2];
    int nchunk = (Cin + 31) >> 5;

    auto loadXreg = [&](int k0c) {
        #pragma unroll
        for (int j = 0; j < 2; ++j) {
            int id = tid + j*256;
            int k = id >> 4, seg = id & 15;
            int kg = k0c + k;
            uint4 v = make_uint4(0u, 0u, 0u, 0u);
            if (kg < Cin)
                v = *reinterpret_cast<const uint4*>(&X[(long)kg*P_TOT + p0 + seg*8]);
            xr[j] = v;
        }
    };
    auto storeX = [&](int k0c, int buf) {
        __half* dst = sXh + buf*XTILE;
        #pragma unroll
        for (int j = 0; j < 2; ++j) {
            int id = tid + j*256;
            int k = id >> 4, seg = id & 15;
            uint4 v = xr[j];
            if (XFORM) {
                int kg = k0c + k;
                if (kg < Cin) {
                    float s = tf_s[kg], h = tf_h[kg], l = tf_l[kg];
                    uint32_t* w = &v.x;
                    #pragma unroll
                    for (int q = 0; q < 4; ++q) {
                        __half2 hv = *reinterpret_cast<__half2*>(&w[q]);
                        float f0 = __low2float(hv), f1 = __high2float(hv);
                        f0 = fmaxf(fmaf(f0, s, h), l);
                        f1 = fmaxf(fmaf(f1, s, h), l);
                        __half2 ho = __floats2half2_rn(f0, f1);
                        w[q] = *reinterpret_cast<uint32_t*>(&ho);
                    }
                }
            }
            int segp = seg ^ (k & 7);
            *reinterpret_cast<uint4*>(&dst[k*128 + segp*8]) = v;
        }
    };
    auto loadWreg = [&](int k0c) {
        #pragma unroll
        for (int j = 0; j < NH2; ++j) {
            int hid = tid + j*256;
            int co = hid >> 4, kp = hid & 15;
            int k = k0c + 2*kp;
            wsf[2*j]   = (k   < Cin) ? A[(long)co*lda + k]   : 0.f;
            wsf[2*j+1] = (k+1 < Cin) ? A[(long)co*lda + k+1] : 0.f;
        }
    };
    auto storeW = [&](int buf) {
        __half* dst = sWh + buf*WTILE;
        #pragma unroll
        for (int j = 0; j < NH2; ++j) {
            int hid = tid + j*256;
            int co = hid >> 4, kp = hid & 15;
            __half2 hp = __floats2half2_rn(wsf[2*j], wsf[2*j+1]);
            *reinterpret_cast<__half2*>(&dst[co*40 + 2*kp]) = hp;
        }
    };

    auto mmaPhase = [&](int buf) {
        const __half* sW = sWh + buf*WTILE;
        uint32_t sX_base = sX_base0 + (uint32_t)(buf*XTILE*2);
        int mi = lane >> 3, lr = lane & 7;
        #pragma unroll
        for (int g16 = 0; g16 < 32; g16 += 16) {
            uint32_t a[MF][4];
            #pragma unroll
            for (int mf = 0; mf < MF; ++mf) {
                int r = warpM*MW + mf*16 + gid;
                a[mf][0] = *reinterpret_cast<const uint32_t*>(&sW[r*40 + g16 + 2*tig]);
                a[mf][1] = *reinterpret_cast<const uint32_t*>(&sW[(r+8)*40 + g16 + 2*tig]);
                a[mf][2] = *reinterpret_cast<const uint32_t*>(&sW[r*40 + g16 + 2*tig + 8]);
                a[mf][3] = *reinterpret_cast<const uint32_t*>(&sW[(r+8)*40 + g16 + 2*tig + 8]);
            }
            int kl = g16 + ((mi & 1) << 3) + lr;
            #pragma unroll
            for (int np = 0; np < 4; ++np) {
                int seg = warpN*8 + np*2 + (mi >> 1);
                int segp = seg ^ (kl & 7);
                uint32_t addr = sX_base + (uint32_t)((kl*128 + segp*8) * 2);
                uint32_t b0, b1, b2, b3;
                ldsm_x4_trans(b0, b1, b2, b3, addr);
                #pragma unroll
                for (int mf = 0; mf < MF; ++mf) {
                    mma_f16(d[mf][2*np],   a[mf][0], a[mf][1], a[mf][2], a[mf][3], b0, b1);
                    mma_f16(d[mf][2*np+1], a[mf][0], a[mf][1], a[mf][2], a[mf][3], b2, b3);
                }
            }
        }
    };

    loadXreg(0);
    loadWreg(0);
    if (XFORM) __syncthreads();
    storeX(0, 0);
    storeW(0);
    __syncthreads();
    for (int c0 = 0; c0 < nchunk; ++c0) {
        int cur = c0 & 1;
        if (c0 + 1 < nchunk) { loadXreg((c0+1)*32); loadWreg((c0+1)*32); }
        mmaPhase(cur);
        if (c0 + 1 < nchunk) {
            storeX((c0+1)*32, 1 - cur);
            storeW(1 - cur);
            __syncthreads();
        }
    }

    // epilogue
    #pragma unroll
    for (int mf = 0; mf < MF; ++mf) {
        int r = warpM*MW + mf*16 + gid;
        int co0 = r, co1 = r + 8;
        float bb0 = bias ? bias[co0] : 0.f;
        float bb1 = bias ? bias[co1] : 0.f;
        double s0 = 0.0, q0 = 0.0, s1 = 0.0, q1 = 0.0;
        float mxa[2], mna[2], mxb[2], mnb[2];
        if (POOL) {
            mxa[0] = mxa[1] = mxb[0] = mxb[1] = -3.4e38f;
            mna[0] = mna[1] = mnb[0] = mnb[1] =  3.4e38f;
        }
        #pragma unroll
        for (int nf = 0; nf < 8; ++nf) {
            int p = p0 + warpN*64 + nf*8 + 2*tig;
            float o0 = d[mf][nf][0] + bb0, o1 = d[mf][nf][1] + bb0;
            float o2 = d[mf][nf][2] + bb1, o3 = d[mf][nf][3] + bb1;
            if (!POOL) {
                *reinterpret_cast<__half2*>(&Y[(long)co0*P_TOT + p]) = __floats2half2_rn(o0, o1);
                *reinterpret_cast<__half2*>(&Y[(long)co1*P_TOT + p]) = __floats2half2_rn(o2, o3);
            } else {
                int g = nf >> 2;
                mxa[g] = fmaxf(mxa[g], fmaxf(o0, o1));
                mna[g] = fminf(mna[g], fminf(o0, o1));
                mxb[g] = fmaxf(mxb[g], fmaxf(o2, o3));
                mnb[g] = fminf(mnb[g], fminf(o2, o3));
            }
            if (STATS) {
                s0 += (double)o0 + (double)o1;
                q0 += (double)o0*o0 + (double)o1*o1;
                s1 += (double)o2 + (double)o3;
                q1 += (double)o2*o2 + (double)o3*o3;
            }
        }
        if (POOL) {
            const int PS = P_TOT >> 5;
            #pragma unroll
            for (int g = 0; g < 2; ++g) {
                float ma = mxa[g], na = mna[g], mb = mxb[g], nb = mnb[g];
                #pragma unroll
                for (int off = 1; off <= 2; off <<= 1) {
                    ma = fmaxf(ma, __shfl_xor_sync(0xFFFFFFFFu, ma, off));
                    na = fminf(na, __shfl_xor_sync(0xFFFFFFFFu, na, off));
                    mb = fmaxf(mb, __shfl_xor_sync(0xFFFFFFFFu, mb, off));
                    nb = fminf(nb, __shfl_xor_sync(0xFFFFFFFFu, nb, off));
                }
                if (tig == 0) {
                    int ps = (p0 >> 5) + warpN*2 + g;
                    pmax[(long)co0*PS + ps] = ma;
                    pmin[(long)co0*PS + ps] = na;
                    pmax[(long)co1*PS + ps] = mb;
                    pmin[(long)co1*PS + ps] = nb;
                }
            }
        }
        if (STATS) {
            #pragma unroll
            for (int off = 1; off <= 2; off <<= 1) {
                s0 += __shfl_xor_sync(0xFFFFFFFFu, s0, off);
                q0 += __shfl_xor_sync(0xFFFFFFFFu, q0, off);
                s1 += __shfl_xor_sync(0xFFFFFFFFu, s1, off);
                q1 += __shfl_xor_sync(0xFFFFFFFFu, q1, off);
            }
            if (tig == 0) {
                atomicAdd(&ssum[co0], s0);
                atomicAdd(&ssq[co0], q0);
                atomicAdd(&ssum[co1], s1);
                atomicAdd(&ssq[co1], q1);
            }
        }
    }
}

// ================= fp32/tf32 GEMM (attention; single-buffer) =================
template<int COUT, bool TRANSA, bool SUB, bool PSCALE, bool STATS>
__global__ void __launch_bounds__(256)
gemm_tc(const float* __restrict__ A, int lda, long aStride,
        const float* __restrict__ X, const float* __restrict__ X2, long xStride,
        const float* __restrict__ pscale, int psStride,
        float* __restrict__ Y, long yStride,
        const float* __restrict__ bias,
        double* __restrict__ ssum, double* __restrict__ ssq,
        int Cin, int P)
{
    constexpr int MW = COUT / 4;
    constexpr int MF = MW / 16;
    constexpr int NW = (COUT*32)/256;
    extern __shared__ char xsm[];
    uint32_t* sX = (uint32_t*)xsm;              // 32*136
    uint32_t* sW = sX + 32*136;                 // COUT*36

    int by = blockIdx.y;
    A += (long)by * aStride;
    X += (long)by * xStride;
    if (SUB) X2 += (long)by * xStride;
    Y += (long)by * yStride;
    int coBase = blockIdx.z * COUT;
    int p0 = blockIdx.x * 128;
    const float* psc = PSCALE ? (pscale + (long)by*psStride + p0) : nullptr;

    int tid = threadIdx.x;
    int lane = tid & 31, wid = tid >> 5;
    int warpM = wid >> 1, warpN = wid & 1;
    int gid = lane >> 2, tig = lane & 3;

    float d[MF][8][4];
    #pragma unroll
    for (int mf = 0; mf < MF; ++mf)
        #pragma unroll
        for (int nf = 0; nf < 8; ++nf)
            #pragma unroll
            for (int i = 0; i < 4; ++i) d[mf][nf][i] = 0.f;

    uint32_t xs[16];
    uint32_t ws[NW];
    int nchunk = (Cin + 31) >> 5;

    auto loadX_g = [&](int k0) {
        #pragma unroll
        for (int j = 0; j < 4; ++j) {
            int id = tid + j*256;
            int row = id >> 5, c4 = id & 31;
            int k = k0 + row;
            float4 v = make_float4(0.f, 0.f, 0.f, 0.f);
            if (k < Cin) {
                v = *reinterpret_cast<const float4*>(&X[(long)k*P + p0 + c4*4]);
                if (SUB) {
                    float4 u = *reinterpret_cast<const float4*>(&X2[(long)k*P + p0 + c4*4]);
                    v.x -= u.x; v.y -= u.y; v.z -= u.z; v.w -= u.w;
                }
                if (PSCALE) {
                    float4 pv = *reinterpret_cast<const float4*>(&psc[c4*4]);
                    v.x *= pv.x; v.y *= pv.y; v.z *= pv.z; v.w *= pv.w;
                }
            }
            xs[j*4+0] = f2tf32(v.x); xs[j*4+1] = f2tf32(v.y);
            xs[j*4+2] = f2tf32(v.z); xs[j*4+3] = f2tf32(v.w);
        }
    };
    auto loadW = [&](int k0) {
        #pragma unroll
        for (int j = 0; j < NW; ++j) {
            int id = tid + j*256;
            int co = id >> 5, kk = id & 31;
            int k = k0 + kk;
            float w = 0.f;
            if (k < Cin)
                w = TRANSA ? A[(long)k*lda + coBase + co]
                           : A[(long)(coBase + co)*lda + k];
            ws[j] = f2tf32(w);
        }
    };
    auto storeTiles = [&]() {
        #pragma unroll
        for (int j = 0; j < 4; ++j) {
            int id = tid + j*256;
            int row = id >> 5, c4 = id & 31;
            *reinterpret_cast<uint4*>(sX + row*136 + c4*4) =
                make_uint4(xs[j*4], xs[j*4+1], xs[j*4+2], xs[j*4+3]);
        }
        #pragma unroll
        for (int j = 0; j < NW; ++j) {
            int id = tid + j*256;
            int co = id >> 5, kk = id & 31;
            sW[co*36 + kk] = ws[j];
        }
    };
    auto mmaPhase = [&]() {
        #pragma unroll
        for (int k8 = 0; k8 < 4; ++k8) {
            int kb = k8*8;
            uint32_t a[MF][4];
            #pragma unroll
            for (int mf = 0; mf < MF; ++mf) {
                int r = warpM*MW + mf*16 + gid;
                a[mf][0] = sW[r*36 + kb + tig];
                a[mf][1] = sW[(r+8)*36 + kb + tig];
                a[mf][2] = sW[r*36 + kb + tig + 4];
                a[mf][3] = sW[(r+8)*36 + kb + tig + 4];
            }
            #pragma unroll
            for (int nf = 0; nf < 8; ++nf) {
                int col = warpN*64 + nf*8 + gid;
                uint32_t b0 = sX[(kb + tig)*136 + col];
                uint32_t b1 = sX[(kb + tig + 4)*136 + col];
                #pragma unroll
                for (int mf = 0; mf < MF; ++mf)
                    mma_tf32(d[mf][nf], a[mf][0], a[mf][1], a[mf][2], a[mf][3], b0, b1);
            }
        }
    };

    loadX_g(0);
    loadW(0);
    for (int c0 = 0; c0 < nchunk; ++c0) {
        storeTiles();
        __syncthreads();
        if (c0 + 1 < nchunk) { loadX_g((c0+1)*32); loadW((c0+1)*32); }
        mmaPhase();
        __syncthreads();
    }

    #pragma unroll
    for (int mf = 0; mf < MF; ++mf) {
        int r = warpM*MW + mf*16 + gid;
        int co0 = coBase + r, co1 = co0 + 8;
        float bb0 = bias ? bias[co0] : 0.f;
        float bb1 = bias ? bias[co1] : 0.f;
        double s0 = 0.0, q0 = 0.0, s1 = 0.0, q1 = 0.0;
        #pragma unroll
        for (int nf = 0; nf < 8; ++nf) {
            int p = p0 + warpN*64 + nf*8 + 2*tig;
            float o0 = d[mf][nf][0] + bb0, o1 = d[mf][nf][1] + bb0;
            float o2 = d[mf][nf][2] + bb1, o3 = d[mf][nf][3] + bb1;
            *reinterpret_cast<float2*>(&Y[(long)co0*P + p]) = make_float2(o0, o1);
            *reinterpret_cast<float2*>(&Y[(long)co1*P + p]) = make_float2(o2, o3);
            if (STATS) {
                s0 += (double)o0 + (double)o1;
                q0 += (double)o0*o0 + (double)o1*o1;
                s1 += (double)o2 + (double)o3;
                q1 += (double)o2*o2 + (double)o3*o3;
            }
        }
        if (STATS) {
            #pragma unroll
            for (int off = 1; off <= 2; off <<= 1) {
                s0 += __shfl_xor_sync(0xFFFFFFFFu, s0, off);
                q0 += __shfl_xor_sync(0xFFFFFFFFu, q0, off);
                s1 += __shfl_xor_sync(0xFFFFFFFFu, s1, off);
                q1 += __shfl_xor_sync(0xFFFFFFFFu, q1, off);
            }
            if (tig == 0) {
                atomicAdd(&ssum[co0], s0);
                atomicAdd(&ssq[co0], q0);
                atomicAdd(&ssum[co1], s1);
                atomicAdd(&ssq[co1], q1);
            }
        }
    }
}

// ---------------- pooled BN+ReLU finalize (inline affine): xp[b][c][s] ----------------
__global__ void __launch_bounds__(256) pool_finalize(float* __restrict__ xp,
                              const float* __restrict__ pmax, const float* __restrict__ pmin,
                              const double* __restrict__ bssum, const double* __restrict__ bssq,
                              const float* __restrict__ bg, const float* __restrict__ bbe) {
    __shared__ float tf_s[128], tf_h[128];
    int tid = threadIdx.x;
    if (tid < 128) {
        double m = bssum[tid] / (double)P_TOT;
        double v = bssq[tid] / (double)P_TOT - m*m;
        float sc = bg[tid] * rsqrtf((float)v + EPSF);
        tf_s[tid] = sc;
        tf_h[tid] = bbe[tid] - (float)m * sc;
    }
    __syncthreads();
    int i = blockIdx.x*256 + tid;
    if (i >= BB*128*NPT) return;
    int s = i & 511, c = (i >> 9) & 127, b = i >> 16;
    int src = c*(BB*NPT) + b*NPT + s;
    float sc = tf_s[c], sh = tf_h[c];
    float v = (sc >= 0.f) ? pmax[src] : pmin[src];
    xp[i] = fmaxf(fmaf(v, sc, sh), 0.f);
}

// ---------------- softmax rows (fast exp) ----------------
__global__ void softmax_kernel(float* __restrict__ e) {
    int gw = (blockIdx.x*256 + threadIdx.x) >> 5;
    int lane = threadIdx.x & 31;
    if (gw >= BB*NPT) return;
    float* row = e + (long)gw * NPT;
    float v[16];
    float mx = -3.4e38f;
    #pragma unroll
    for (int i = 0; i < 16; ++i) { v[i] = row[lane + i*32]; mx = fmaxf(mx, v[i]); }
    #pragma unroll
    for (int off = 16; off > 0; off >>= 1)
        mx = fmaxf(mx, __shfl_xor_sync(0xFFFFFFFFu, mx, off));
    float sum = 0.f;
    #pragma unroll
    for (int i = 0; i < 16; ++i) { v[i] = __expf(v[i] - mx); sum += v[i]; }
    #pragma unroll
    for (int off = 16; off > 0; off >>= 1)
        sum += __shfl_xor_sync(0xFFFFFFFFu, sum, off);
    float inv = 1.f / sum;
    #pragma unroll
    for (int i = 0; i < 16; ++i) row[lane + i*32] = v[i] * inv;
}

// ---------------- column sums (store reciprocal) ----------------
__global__ void colsum_kernel(const float* __restrict__ e, float* __restrict__ colrcp) {
    int b = blockIdx.x, m = blockIdx.y*128 + threadIdx.x;
    const float* E = e + (long)b * NPT * NPT;
    float s = 0.f;
    for (int n = 0; n < NPT; ++n) s += E[n*NPT + m];
    colrcp[b*NPT + m] = 1.f / (1e-9f + s);
}

// ---------------- final residual (inline bn1d affine) ----------------
__global__ void __launch_bounds__(256) final_kernel(float* __restrict__ out,
                             const float* __restrict__ xp,
                             const float* __restrict__ y,
                             const double* __restrict__ bssum, const double* __restrict__ bssq,
                             const float* __restrict__ bg, const float* __restrict__ bbe,
                             const float* __restrict__ alpha, const float* __restrict__ beta) {
    __shared__ float tf_s[128], tf_h[128];
    int tid = threadIdx.x;
    if (tid < 128) {
        double m = bssum[tid] / (double)(BB*NPT);
        double v = bssq[tid] / (double)(BB*NPT) - m*m;
        float sc = bg[tid] * rsqrtf((float)v + EPSF);
        tf_s[tid] = sc;
        tf_h[tid] = bbe[tid] - (float)m * sc;
    }
    __syncthreads();
    int i = blockIdx.x*256 + tid;
    if (i >= BB*128*NPT) return;
    int c = (i >> 9) & 127;
    float xr = fmaxf(fmaf(y[i], tf_s[c], tf_h[c]), 0.f);
    out[i] = xp[i] + alpha[c]*xr + beta[c];
}

// ---------------- launch ----------------
extern "C" void kernel_launch(void* const* d_in, const int* in_sizes, int n_in,
                              void* d_out, int out_size) {
    const float* xyz    = (const float*)d_in[0];
    const float* points = (const float*)d_in[1];
    const float* w0 = (const float*)d_in[2];
    const float* b0 = (const float*)d_in[3];
    const float* g0 = (const float*)d_in[4];
    const float* be0= (const float*)d_in[5];
    const float* w1 = (const float*)d_in[6];
    const float* b1 = (const float*)d_in[7];
    const float* g1 = (const float*)d_in[8];
    const float* be1= (const float*)d_in[9];
    const float* w2 = (const float*)d_in[10];
    const float* b2 = (const float*)d_in[11];
    const float* g2 = (const float*)d_in[12];
    const float* be2= (const float*)d_in[13];
    const float* wl = (const float*)d_in[14];
    const float* bl = (const float*)d_in[15];
    const float* gl = (const float*)d_in[16];
    const float* bel= (const float*)d_in[17];
    const float* wv = (const float*)d_in[18];
    const float* bv = (const float*)d_in[19];
    const float* wt = (const float*)d_in[20];
    const float* bt = (const float*)d_in[21];
    const float* gn = (const float*)d_in[22];
    const float* gb = (const float*)d_in[23];
    const float* alpha = (const float*)d_in[24];
    const float* beta  = (const float*)d_in[25];
    float* out = (float*)d_out;

    float *xp, *x0, *energy, *x2, *y, *colrcp, *pmax, *pmin;
    __half *hA, *hB;
    double *ssum, *ssq;
    int *fps, *nbr;
    cudaGetSymbolAddress((void**)&hA, g_hA);
    cudaGetSymbolAddress((void**)&hB, g_hB);
    cudaGetSymbolAddress((void**)&xp, g_xp);
    cudaGetSymbolAddress((void**)&x0, g_x0);
    cudaGetSymbolAddress((void**)&energy, g_energy);
    cudaGetSymbolAddress((void**)&x2, g_x2);
    cudaGetSymbolAddress((void**)&y, g_y);
    cudaGetSymbolAddress((void**)&ssum, g_ssum);
    cudaGetSymbolAddress((void**)&ssq, g_ssq);
    cudaGetSymbolAddress((void**)&colrcp, g_colrcp);
    cudaGetSymbolAddress((void**)&pmax, g_pmax);
    cudaGetSymbolAddress((void**)&pmin, g_pmin);
    cudaGetSymbolAddress((void**)&fps, g_fps);
    cudaGetSymbolAddress((void**)&nbr, g_nbr);

    const int SMEM_PTS = 3*NN*sizeof(float);   // 48KB
    cudaFuncSetAttribute(fps_kernel,  cudaFuncAttributeMaxDynamicSharedMemorySize, 64*1024);
    cudaFuncSetAttribute(ball_kernel, cudaFuncAttributeMaxDynamicSharedMemorySize, 64*1024);

    const int SM_H64  = 2*(32*128 + 64*40) * 2;    // 26624
    const int SM_H128 = 2*(32*128 + 128*40) * 2;   // 36864
    const int SM_N128 = 32*136*4 + 128*36*4;       // 35840
    const int SM_N64  = 32*136*4 + 64*36*4;        // 26624

    // geometry (4th launch = L0 fp16 GEMM for ncu capture)
    fps_kernel<<<BB, 1024, SMEM_PTS>>>(xyz, fps);
    ball_kernel<<<dim3(NPT/8, BB), 256, SMEM_PTS>>>(xyz, fps, nbr);
    feat_kernel<<<dim3(NPT, BB), 256>>>(points, xyz, fps, nbr, hB, hA + 128L*P_TOT);

    // L0: 128->64, stats slot0
    gemm_h<64,false,true,false><<<P_TOT/128, 256, SM_H64>>>(
        w0, 128, hB, hA, b0, nullptr, nullptr, nullptr, nullptr, 0,
        ssum+0, ssq+0, nullptr, nullptr, 128);
    newxyz_kernel<<<(BB*3*NPT + 255)/256, 256>>>(out, xyz, fps);

    // L1: 64->64, xform from slot0 stats (g0/be0), stats slot1
    gemm_h<64,true,true,false><<<P_TOT/128, 256, SM_H64>>>(
        w1, 64, hA, hB, b1, ssum+0, ssq+0, g0, be0, 64,
        ssum+128, ssq+128, nullptr, nullptr, 64);

    // L2: 64->128, xform from slot1 (g1/be1), stats slot2
    gemm_h<128,true,true,false><<<P_TOT/128, 256, SM_H128>>>(
        w2, 64, hB, hA, b2, ssum+128, ssq+128, g1, be1, 64,
        ssum+256, ssq+256, nullptr, nullptr, 64);

    // Ll: 131->128, xform from slot2 (g2/be2, 128 BN + 3 pass), stats slot3, POOL
    gemm_h<128,true,true,true><<<P_TOT/128, 256, SM_H128>>>(
        wl, 131, hA, nullptr, bl, ssum+256, ssq+256, g2, be2, 128,
        ssum+384, ssq+384, pmax, pmin, 131);
    pool_finalize<<<(BB*128*NPT + 255)/256, 256>>>(xp, pmax, pmin,
        ssum+384, ssq+384, gl, bel);

    // attention (tf32); wv/x2/wt split into COUT=64 tiles for 2x parallelism
    gemm_tc<64,false,false,false,false><<<dim3(NPT/128, BB, 2), 256, SM_N64>>>(
        wv, 128, 0, xp, nullptr, PB, nullptr, 0, x0, PB, bv,
        nullptr, nullptr, 128, NPT);
    gemm_tc<128,true,false,false,false><<<dim3(NPT/128, BB, 4), 256, SM_N128>>>(
        xp, NPT, PB, x0, nullptr, PB, nullptr, 0, energy, (long)NPT*NPT, nullptr,
        nullptr, nullptr, 128, NPT);
    softmax_kernel<<<(BB*NPT*32 + 255)/256, 256>>>(energy);
    colsum_kernel<<<dim3(BB, NPT/128), 128>>>(energy, colrcp);
    gemm_tc<64,false,false,true,false><<<dim3(NPT/128, BB, 2), 256, SM_N64>>>(
        x0, NPT, PB, energy, nullptr, (long)NPT*NPT, colrcp, NPT, x2, PB, nullptr,
        nullptr, nullptr, NPT, NPT);
    gemm_tc<64,false,true,false,true><<<dim3(NPT/128, BB, 2), 256, SM_N64>>>(
        wt, 128, 0, xp, x2, PB, nullptr, 0, y, PB, bt,
        ssum+512, ssq+512, 128, NPT);

    final_kernel<<<(BB*128*NPT + 255)/256, 256>>>(out + BB*3*NPT, xp, y,
        ssum+512, ssq+512, gn, gb, alpha, beta);
}

// round 15
// speedup vs baseline: 1.0270x; 1.0122x over previous
#include <cuda_runtime.h>
#include <cuda_bf16.h>
#include <cuda_fp16.h>
#include <cstdint>
#include <math.h>

// ---------------- constants ----------------
#define BB   16
#define NN   4096
#define DD   64
#define NPT  512
#define KK   32
#define P_TOT (BB*NPT*KK)     // 262144
#define PB   (128*NPT)        // 65536 per-batch (c,s) block
#define EPSF 1e-5f

// ---------------- scratch ----------------
__device__ __half g_hA[131L * P_TOT];           // 131 x P halves (rows 128..130 = rel_xyz)
__device__ __half g_hB[128L * P_TOT];           // 128 x P halves
__device__ float g_xp[BB*128*NPT];
__device__ float g_x0[BB*128*NPT];
__device__ float g_energy[BB*NPT*NPT];
__device__ float g_x2[BB*128*NPT];
__device__ float g_y[BB*128*NPT];
__device__ float g_pmax[128*BB*NPT];
__device__ float g_pmin[128*BB*NPT];
__device__ double g_ssum[5*128];
__device__ double g_ssq[5*128];
__device__ float g_colrcp[BB*NPT];
__device__ int   g_fps[BB*NPT];
__device__ int   g_nbr[BB*NPT*KK];

// ---------------- FPS (single barrier per iteration) ----------------
__global__ void __launch_bounds__(1024) fps_kernel(const float* __restrict__ xyz,
                                                   int* __restrict__ fps) {
    extern __shared__ char xsm[];
    float* sm = (float*)xsm;
    float* sx = sm;
    float* sy = sm + NN;
    float* sz = sm + 2*NN;
    __shared__ unsigned long long swarp[2][32];
    int b = blockIdx.x, tid = threadIdx.x;
    int lane = tid & 31, wid = tid >> 5;
    const float* base = xyz + (long)b*3*NN;
    for (int i = tid; i < NN; i += 1024) {
        sx[i] = base[i];
        sy[i] = base[NN + i];
        sz[i] = base[2*NN + i];
    }
    __syncthreads();
    float dist[4];
    dist[0] = dist[1] = dist[2] = dist[3] = 1e10f;
    int far = 0;
    for (int it = 0; it < NPT; ++it) {
        if (tid == 0) fps[b*NPT + it] = far;
        float cx = sx[far], cy = sy[far], cz = sz[far];
        unsigned long long best = 0ull;
        #pragma unroll
        for (int j = 0; j < 4; ++j) {
            int n = tid + j*1024;
            float dx = sx[n]-cx, dy = sy[n]-cy, dz = sz[n]-cz;
            float d = dx*dx + dy*dy + dz*dz;
            float dd = fminf(dist[j], d);
            dist[j] = dd;
            unsigned long long key =
                ((unsigned long long)__float_as_uint(dd) << 32) |
                (unsigned long long)(0xFFFFFFFFu - (unsigned)n);
            best = (key > best) ? key : best;
        }
        #pragma unroll
        for (int off = 16; off > 0; off >>= 1) {
            unsigned long long o = __shfl_xor_sync(0xFFFFFFFFu, best, off);
            best = (o > best) ? o : best;
        }
        if (lane == 0) swarp[it & 1][wid] = best;
        __syncthreads();
        best = swarp[it & 1][lane];
        #pragma unroll
        for (int off = 16; off > 0; off >>= 1) {
            unsigned long long o = __shfl_xor_sync(0xFFFFFFFFu, best, off);
            best = (o > best) ? o : best;
        }
        far = (int)(0xFFFFFFFFu - (unsigned)(best & 0xFFFFFFFFull));
    }
}

// ---------------- new_xyz output ----------------
__global__ void newxyz_kernel(float* __restrict__ out, const float* __restrict__ xyz,
                              const int* __restrict__ fps) {
    int i = blockIdx.x*256 + threadIdx.x;
    if (i >= BB*3*NPT) return;
    int s = i & 511;
    int c = (i >> 9) % 3;
    int b = i / (3*NPT);
    out[i] = xyz[(long)b*3*NN + c*NN + fps[b*NPT + s]];
}

// ---------------- ball query (512 threads, 16 centers/block) ----------------
__global__ void __launch_bounds__(512) ball_kernel(const float* __restrict__ xyz,
                                                   const int* __restrict__ fps,
                                                   int* __restrict__ nbr) {
    extern __shared__ char xsm[];
    float* sm = (float*)xsm;
    float* sx = sm;
    float* sy = sm + NN;
    float* sz = sm + 2*NN;
    __shared__ int snb[16][KK];
    int b = blockIdx.y, tid = threadIdx.x;
    const float* base = xyz + (long)b*3*NN;
    for (int i = tid; i < NN; i += 512) {
        sx[i] = base[i];
        sy[i] = base[NN + i];
        sz[i] = base[2*NN + i];
    }
    __syncthreads();
    int w = tid >> 5, lane = tid & 31;
    int s = blockIdx.x*16 + w;
    int fi = fps[b*NPT + s];
    float cx = sx[fi], cy = sy[fi], cz = sz[fi];
    float cn = cx*cx + cy*cy + cz*cz;
    const float R2 = (float)(0.4*0.4);
    int cnt = 0;
    for (int n0 = 0; n0 < NN && cnt < KK; n0 += 32) {
        int n = n0 + lane;
        float px = sx[n], py = sy[n], pz = sz[n];
        float pn = px*px + py*py + pz*pz;
        float dt = cx*px + cy*py + cz*pz;
        float sq = (cn + pn) - 2.0f*dt;
        bool in = !(sq > R2);
        unsigned m = __ballot_sync(0xFFFFFFFFu, in);
        int pos = cnt + __popc(m & ((1u << lane) - 1u));
        if (in && pos < KK) snb[w][pos] = n;
        cnt += __popc(m);
    }
    __syncwarp();
    int v = (lane < cnt) ? snb[w][lane] : snb[w][0];
    nbr[(b*NPT + s)*KK + lane] = v;
}

// ---------------- feature build (half output; also zeros BN stats) ----------------
__global__ void __launch_bounds__(256) feat_kernel(const float* __restrict__ points,
                                                   const float* __restrict__ xyz,
                                                   const int* __restrict__ fps,
                                                   const int* __restrict__ nbr,
                                                   __half* __restrict__ X0,
                                                   __half* __restrict__ relbuf) {
    int s = blockIdx.x, b = blockIdx.y, tid = threadIdx.x;
    if (s == 0 && b == 0) {
        for (int i = tid; i < 5*128; i += 256) { g_ssum[i] = 0.0; g_ssq[i] = 0.0; }
    }
    __shared__ int snb[KK];
    __shared__ float scen[DD];
    __shared__ float scxyz[3];
    int fi = fps[b*NPT + s];
    if (tid < KK) snb[tid] = nbr[(b*NPT + s)*KK + tid];
    if (tid >= 32 && tid < 32+DD) scen[tid-32] = points[(long)b*DD*NN + (tid-32)*NN + fi];
    if (tid >= 96 && tid < 99)   scxyz[tid-96] = xyz[(long)b*3*NN + (tid-96)*NN + fi];
    __syncthreads();
    int k = tid & 31, cb = tid >> 5;
    int n = snb[k];
    int base = (b*NPT + s)*KK + k;
    #pragma unroll
    for (int q = 0; q < 8; ++q) {
        int c = q*8 + cb;
        float v = points[(long)b*DD*NN + c*NN + n];
        X0[(long)c*P_TOT + base] = __float2half(v);
        X0[(long)(DD+c)*P_TOT + base] = __float2half(v - scen[c]);
    }
    if (cb < 3) {
        float v = xyz[(long)b*3*NN + cb*NN + n] - scxyz[cb];
        relbuf[(long)cb*P_TOT + base] = __float2half(v);
    }
}

// ---------------- mma helpers ----------------
__device__ __forceinline__ uint32_t f2tf32(float v) {
    uint32_t r;
    asm("cvt.rna.tf32.f32 %0, %1;" : "=r"(r) : "f"(v));
    return r;
}
__device__ __forceinline__ void mma_tf32(float* d, uint32_t a0, uint32_t a1,
                                         uint32_t a2, uint32_t a3,
                                         uint32_t b0, uint32_t b1) {
    asm volatile("mma.sync.aligned.m16n8k8.row.col.f32.tf32.tf32.f32 "
        "{%0,%1,%2,%3},{%4,%5,%6,%7},{%8,%9},{%0,%1,%2,%3};"
        : "+f"(d[0]), "+f"(d[1]), "+f"(d[2]), "+f"(d[3])
        : "r"(a0), "r"(a1), "r"(a2), "r"(a3), "r"(b0), "r"(b1));
}
__device__ __forceinline__ void mma_f16(float* d, uint32_t a0, uint32_t a1,
                                        uint32_t a2, uint32_t a3,
                                        uint32_t b0, uint32_t b1) {
    asm volatile("mma.sync.aligned.m16n8k16.row.col.f32.f16.f16.f32 "
        "{%0,%1,%2,%3},{%4,%5,%6,%7},{%8,%9},{%0,%1,%2,%3};"
        : "+f"(d[0]), "+f"(d[1]), "+f"(d[2]), "+f"(d[3])
        : "r"(a0), "r"(a1), "r"(a2), "r"(a3), "r"(b0), "r"(b1));
}
__device__ __forceinline__ void ldsm_x4_trans(uint32_t& r0, uint32_t& r1,
                                              uint32_t& r2, uint32_t& r3, uint32_t addr) {
    asm volatile("ldmatrix.sync.aligned.m8n8.x4.trans.shared.b16 {%0,%1,%2,%3}, [%4];"
        : "=r"(r0), "=r"(r1), "=r"(r2), "=r"(r3) : "r"(addr));
}

// ================= fp16 big-layer GEMM (double-buffered, 1 sync/chunk) =========
template<int COUT, bool XFORM, bool STATS, bool POOL>
__global__ void __launch_bounds__(256, (COUT == 64) ? 3 : 2)
gemm_h(const float* __restrict__ A, int lda,
       const __half* __restrict__ X,
       __half* __restrict__ Y,
       const float* __restrict__ bias,
       const double* __restrict__ bssum, const double* __restrict__ bssq,
       const float* __restrict__ bg, const float* __restrict__ bbe, int Cbn,
       double* __restrict__ ssum, double* __restrict__ ssq,
       float* __restrict__ pmax, float* __restrict__ pmin,
       int Cin)
{
    constexpr int MW = COUT / 4;
    constexpr int MF = MW / 16;
    constexpr int NH2 = COUT / 16;
    constexpr int XTILE = 32*128;
    constexpr int WTILE = COUT*40;
    extern __shared__ char xsm[];
    __half* sXh = (__half*)xsm;
    __half* sWh = sXh + 2*XTILE;
    __shared__ float tf_s[132], tf_h[132], tf_l[132];

    int p0 = blockIdx.x * 128;
    int tid = threadIdx.x;
    int lane = tid & 31, wid = tid >> 5;
    int warpM = wid >> 1, warpN = wid & 1;
    int gid = lane >> 2, tig = lane & 3;

    if (XFORM) {
        for (int c = tid; c < Cin; c += 256) {
            if (c < Cbn) {
                double m = bssum[c] / (double)P_TOT;
                double v = bssq[c] / (double)P_TOT - m*m;
                float sc = bg[c] * rsqrtf((float)v + EPSF);
                tf_s[c] = sc;
                tf_h[c] = bbe[c] - (float)m * sc;
                tf_l[c] = 0.f;
            } else {
                tf_s[c] = 1.f;
                tf_h[c] = 0.f;
                tf_l[c] = -3.4e38f;
            }
        }
    }

    uint32_t sX_base0 = (uint32_t)__cvta_generic_to_shared(sXh);

    float d[MF][8][4];
    #pragma unroll
    for (int mf = 0; mf < MF; ++mf)
        #pragma unroll
        for (int nf = 0; nf < 8; ++nf)
            #pragma unroll
            for (int i = 0; i < 4; ++i) d[mf][nf][i] = 0.f;

    uint4 xr[2];
    float wsf[2*NH2];
    int nchunk = (Cin + 31) >> 5;

    auto loadXreg = [&](int k0c) {
        #pragma unroll
        for (int j = 0; j < 2; ++j) {
            int id = tid + j*256;
            int k = id >> 4, seg = id & 15;
            int kg = k0c + k;
            uint4 v = make_uint4(0u, 0u, 0u, 0u);
            if (kg < Cin)
                v = *reinterpret_cast<const uint4*>(&X[(long)kg*P_TOT + p0 + seg*8]);
            xr[j] = v;
        }
    };
    auto storeX = [&](int k0c, int buf) {
        __half* dst = sXh + buf*XTILE;
        #pragma unroll
        for (int j = 0; j < 2; ++j) {
            int id = tid + j*256;
            int k = id >> 4, seg = id & 15;
            uint4 v = xr[j];
            if (XFORM) {
                int kg = k0c + k;
                if (kg < Cin) {
                    float s = tf_s[kg], h = tf_h[kg], l = tf_l[kg];
                    uint32_t* w = &v.x;
                    #pragma unroll
                    for (int q = 0; q < 4; ++q) {
                        __half2 hv = *reinterpret_cast<__half2*>(&w[q]);
                        float f0 = __low2float(hv), f1 = __high2float(hv);
                        f0 = fmaxf(fmaf(f0, s, h), l);
                        f1 = fmaxf(fmaf(f1, s, h), l);
                        __half2 ho = __floats2half2_rn(f0, f1);
                        w[q] = *reinterpret_cast<uint32_t*>(&ho);
                    }
                }
            }
            int segp = seg ^ (k & 7);
            *reinterpret_cast<uint4*>(&dst[k*128 + segp*8]) = v;
        }
    };
    auto loadWreg = [&](int k0c) {
        #pragma unroll
        for (int j = 0; j < NH2; ++j) {
            int hid = tid + j*256;
            int co = hid >> 4, kp = hid & 15;
            int k = k0c + 2*kp;
            wsf[2*j]   = (k   < Cin) ? A[(long)co*lda + k]   : 0.f;
            wsf[2*j+1] = (k+1 < Cin) ? A[(long)co*lda + k+1] : 0.f;
        }
    };
    auto storeW = [&](int buf) {
        __half* dst = sWh + buf*WTILE;
        #pragma unroll
        for (int j = 0; j < NH2; ++j) {
            int hid = tid + j*256;
            int co = hid >> 4, kp = hid & 15;
            __half2 hp = __floats2half2_rn(wsf[2*j], wsf[2*j+1]);
            *reinterpret_cast<__half2*>(&dst[co*40 + 2*kp]) = hp;
        }
    };

    auto mmaPhase = [&](int buf) {
        const __half* sW = sWh + buf*WTILE;
        uint32_t sX_base = sX_base0 + (uint32_t)(buf*XTILE*2);
        int mi = lane >> 3, lr = lane & 7;
        #pragma unroll
        for (int g16 = 0; g16 < 32; g16 += 16) {
            uint32_t a[MF][4];
            #pragma unroll
            for (int mf = 0; mf < MF; ++mf) {
                int r = warpM*MW + mf*16 + gid;
                a[mf][0] = *reinterpret_cast<const uint32_t*>(&sW[r*40 + g16 + 2*tig]);
                a[mf][1] = *reinterpret_cast<const uint32_t*>(&sW[(r+8)*40 + g16 + 2*tig]);
                a[mf][2] = *reinterpret_cast<const uint32_t*>(&sW[r*40 + g16 + 2*tig + 8]);
                a[mf][3] = *reinterpret_cast<const uint32_t*>(&sW[(r+8)*40 + g16 + 2*tig + 8]);
            }
            int kl = g16 + ((mi & 1) << 3) + lr;
            #pragma unroll
            for (int np = 0; np < 4; ++np) {
                int seg = warpN*8 + np*2 + (mi >> 1);
                int segp = seg ^ (kl & 7);
                uint32_t addr = sX_base + (uint32_t)((kl*128 + segp*8) * 2);
                uint32_t b0, b1, b2, b3;
                ldsm_x4_trans(b0, b1, b2, b3, addr);
                #pragma unroll
                for (int mf = 0; mf < MF; ++mf) {
                    mma_f16(d[mf][2*np],   a[mf][0], a[mf][1], a[mf][2], a[mf][3], b0, b1);
                    mma_f16(d[mf][2*np+1], a[mf][0], a[mf][1], a[mf][2], a[mf][3], b2, b3);
                }
            }
        }
    };

    loadXreg(0);
    loadWreg(0);
    if (XFORM) __syncthreads();
    storeX(0, 0);
    storeW(0);
    __syncthreads();
    for (int c0 = 0; c0 < nchunk; ++c0) {
        int cur = c0 & 1;
        if (c0 + 1 < nchunk) { loadXreg((c0+1)*32); loadWreg((c0+1)*32); }
        mmaPhase(cur);
        if (c0 + 1 < nchunk) {
            storeX((c0+1)*32, 1 - cur);
            storeW(1 - cur);
            __syncthreads();
        }
    }

    // epilogue
    #pragma unroll
    for (int mf = 0; mf < MF; ++mf) {
        int r = warpM*MW + mf*16 + gid;
        int co0 = r, co1 = r + 8;
        float bb0 = bias ? bias[co0] : 0.f;
        float bb1 = bias ? bias[co1] : 0.f;
        double s0 = 0.0, q0 = 0.0, s1 = 0.0, q1 = 0.0;
        float mxa[2], mna[2], mxb[2], mnb[2];
        if (POOL) {
            mxa[0] = mxa[1] = mxb[0] = mxb[1] = -3.4e38f;
            mna[0] = mna[1] = mnb[0] = mnb[1] =  3.4e38f;
        }
        #pragma unroll
        for (int nf = 0; nf < 8; ++nf) {
            int p = p0 + warpN*64 + nf*8 + 2*tig;
            float o0 = d[mf][nf][0] + bb0, o1 = d[mf][nf][1] + bb0;
            float o2 = d[mf][nf][2] + bb1, o3 = d[mf][nf][3] + bb1;
            if (!POOL) {
                *reinterpret_cast<__half2*>(&Y[(long)co0*P_TOT + p]) = __floats2half2_rn(o0, o1);
                *reinterpret_cast<__half2*>(&Y[(long)co1*P_TOT + p]) = __floats2half2_rn(o2, o3);
            } else {
                int g = nf >> 2;
                mxa[g] = fmaxf(mxa[g], fmaxf(o0, o1));
                mna[g] = fminf(mna[g], fminf(o0, o1));
                mxb[g] = fmaxf(mxb[g], fmaxf(o2, o3));
                mnb[g] = fminf(mnb[g], fminf(o2, o3));
            }
            if (STATS) {
                s0 += (double)o0 + (double)o1;
                q0 += (double)o0*o0 + (double)o1*o1;
                s1 += (double)o2 + (double)o3;
                q1 += (double)o2*o2 + (double)o3*o3;
            }
        }
        if (POOL) {
            const int PS = P_TOT >> 5;
            #pragma unroll
            for (int g = 0; g < 2; ++g) {
                float ma = mxa[g], na = mna[g], mb = mxb[g], nb = mnb[g];
                #pragma unroll
                for (int off = 1; off <= 2; off <<= 1) {
                    ma = fmaxf(ma, __shfl_xor_sync(0xFFFFFFFFu, ma, off));
                    na = fminf(na, __shfl_xor_sync(0xFFFFFFFFu, na, off));
                    mb = fmaxf(mb, __shfl_xor_sync(0xFFFFFFFFu, mb, off));
                    nb = fminf(nb, __shfl_xor_sync(0xFFFFFFFFu, nb, off));
                }
                if (tig == 0) {
                    int ps = (p0 >> 5) + warpN*2 + g;
                    pmax[(long)co0*PS + ps] = ma;
                    pmin[(long)co0*PS + ps] = na;
                    pmax[(long)co1*PS + ps] = mb;
                    pmin[(long)co1*PS + ps] = nb;
                }
            }
        }
        if (STATS) {
            #pragma unroll
            for (int off = 1; off <= 2; off <<= 1) {
                s0 += __shfl_xor_sync(0xFFFFFFFFu, s0, off);
                q0 += __shfl_xor_sync(0xFFFFFFFFu, q0, off);
                s1 += __shfl_xor_sync(0xFFFFFFFFu, s1, off);
                q1 += __shfl_xor_sync(0xFFFFFFFFu, q1, off);
            }
            if (tig == 0) {
                atomicAdd(&ssum[co0], s0);
                atomicAdd(&ssq[co0], q0);
                atomicAdd(&ssum[co1], s1);
                atomicAdd(&ssq[co1], q1);
            }
        }
    }
}

// ================= fp32/tf32 GEMM (attention; single-buffer) =================
template<int COUT, bool TRANSA, bool SUB, bool PSCALE, bool STATS>
__global__ void __launch_bounds__(256)
gemm_tc(const float* __restrict__ A, int lda, long aStride,
        const float* __restrict__ X, const float* __restrict__ X2, long xStride,
        const float* __restrict__ pscale, int psStride,
        float* __restrict__ Y, long yStride,
        const float* __restrict__ bias,
        double* __restrict__ ssum, double* __restrict__ ssq,
        int Cin, int P)
{
    constexpr int MW = COUT / 4;
    constexpr int MF = MW / 16;
    constexpr int NW = (COUT*32)/256;
    extern __shared__ char xsm[];
    uint32_t* sX = (uint32_t*)xsm;              // 32*136
    uint32_t* sW = sX + 32*136;                 // COUT*36

    int by = blockIdx.y;
    A += (long)by * aStride;
    X += (long)by * xStride;
    if (SUB) X2 += (long)by * xStride;
    Y += (long)by * yStride;
    int coBase = blockIdx.z * COUT;
    int p0 = blockIdx.x * 128;
    const float* psc = PSCALE ? (pscale + (long)by*psStride + p0) : nullptr;

    int tid = threadIdx.x;
    int lane = tid & 31, wid = tid >> 5;
    int warpM = wid >> 1, warpN = wid & 1;
    int gid = lane >> 2, tig = lane & 3;

    float d[MF][8][4];
    #pragma unroll
    for (int mf = 0; mf < MF; ++mf)
        #pragma unroll
        for (int nf = 0; nf < 8; ++nf)
            #pragma unroll
            for (int i = 0; i < 4; ++i) d[mf][nf][i] = 0.f;

    uint32_t xs[16];
    uint32_t ws[NW];
    int nchunk = (Cin + 31) >> 5;

    auto loadX_g = [&](int k0) {
        #pragma unroll
        for (int j = 0; j < 4; ++j) {
            int id = tid + j*256;
            int row = id >> 5, c4 = id & 31;
            int k = k0 + row;
            float4 v = make_float4(0.f, 0.f, 0.f, 0.f);
            if (k < Cin) {
                v = *reinterpret_cast<const float4*>(&X[(long)k*P + p0 + c4*4]);
                if (SUB) {
                    float4 u = *reinterpret_cast<const float4*>(&X2[(long)k*P + p0 + c4*4]);
                    v.x -= u.x; v.y -= u.y; v.z -= u.z; v.w -= u.w;
                }
                if (PSCALE) {
                    float4 pv = *reinterpret_cast<const float4*>(&psc[c4*4]);
                    v.x *= pv.x; v.y *= pv.y; v.z *= pv.z; v.w *= pv.w;
                }
            }
            xs[j*4+0] = f2tf32(v.x); xs[j*4+1] = f2tf32(v.y);
            xs[j*4+2] = f2tf32(v.z); xs[j*4+3] = f2tf32(v.w);
        }
    };
    auto loadW = [&](int k0) {
        #pragma unroll
        for (int j = 0; j < NW; ++j) {
            int id = tid + j*256;
            int co = id >> 5, kk = id & 31;
            int k = k0 + kk;
            float w = 0.f;
            if (k < Cin)
                w = TRANSA ? A[(long)k*lda + coBase + co]
                           : A[(long)(coBase + co)*lda + k];
            ws[j] = f2tf32(w);
        }
    };
    auto storeTiles = [&]() {
        #pragma unroll
        for (int j = 0; j < 4; ++j) {
            int id = tid + j*256;
            int row = id >> 5, c4 = id & 31;
            *reinterpret_cast<uint4*>(sX + row*136 + c4*4) =
                make_uint4(xs[j*4], xs[j*4+1], xs[j*4+2], xs[j*4+3]);
        }
        #pragma unroll
        for (int j = 0; j < NW; ++j) {
            int id = tid + j*256;
            int co = id >> 5, kk = id & 31;
            sW[co*36 + kk] = ws[j];
        }
    };
    auto mmaPhase = [&]() {
        #pragma unroll
        for (int k8 = 0; k8 < 4; ++k8) {
            int kb = k8*8;
            uint32_t a[MF][4];
            #pragma unroll
            for (int mf = 0; mf < MF; ++mf) {
                int r = warpM*MW + mf*16 + gid;
                a[mf][0] = sW[r*36 + kb + tig];
                a[mf][1] = sW[(r+8)*36 + kb + tig];
                a[mf][2] = sW[r*36 + kb + tig + 4];
                a[mf][3] = sW[(r+8)*36 + kb + tig + 4];
            }
            #pragma unroll
            for (int nf = 0; nf < 8; ++nf) {
                int col = warpN*64 + nf*8 + gid;
                uint32_t b0 = sX[(kb + tig)*136 + col];
                uint32_t b1 = sX[(kb + tig + 4)*136 + col];
                #pragma unroll
                for (int mf = 0; mf < MF; ++mf)
                    mma_tf32(d[mf][nf], a[mf][0], a[mf][1], a[mf][2], a[mf][3], b0, b1);
            }
        }
    };

    loadX_g(0);
    loadW(0);
    for (int c0 = 0; c0 < nchunk; ++c0) {
        storeTiles();
        __syncthreads();
        if (c0 + 1 < nchunk) { loadX_g((c0+1)*32); loadW((c0+1)*32); }
        mmaPhase();
        __syncthreads();
    }

    #pragma unroll
    for (int mf = 0; mf < MF; ++mf) {
        int r = warpM*MW + mf*16 + gid;
        int co0 = coBase + r, co1 = co0 + 8;
        float bb0 = bias ? bias[co0] : 0.f;
        float bb1 = bias ? bias[co1] : 0.f;
        double s0 = 0.0, q0 = 0.0, s1 = 0.0, q1 = 0.0;
        #pragma unroll
        for (int nf = 0; nf < 8; ++nf) {
            int p = p0 + warpN*64 + nf*8 + 2*tig;
            float o0 = d[mf][nf][0] + bb0, o1 = d[mf][nf][1] + bb0;
            float o2 = d[mf][nf][2] + bb1, o3 = d[mf][nf][3] + bb1;
            *reinterpret_cast<float2*>(&Y[(long)co0*P + p]) = make_float2(o0, o1);
            *reinterpret_cast<float2*>(&Y[(long)co1*P + p]) = make_float2(o2, o3);
            if (STATS) {
                s0 += (double)o0 + (double)o1;
                q0 += (double)o0*o0 + (double)o1*o1;
                s1 += (double)o2 + (double)o3;
                q1 += (double)o2*o2 + (double)o3*o3;
            }
        }
        if (STATS) {
            #pragma unroll
            for (int off = 1; off <= 2; off <<= 1) {
                s0 += __shfl_xor_sync(0xFFFFFFFFu, s0, off);
                q0 += __shfl_xor_sync(0xFFFFFFFFu, q0, off);
                s1 += __shfl_xor_sync(0xFFFFFFFFu, s1, off);
                q1 += __shfl_xor_sync(0xFFFFFFFFu, q1, off);
            }
            if (tig == 0) {
                atomicAdd(&ssum[co0], s0);
                atomicAdd(&ssq[co0], q0);
                atomicAdd(&ssum[co1], s1);
                atomicAdd(&ssq[co1], q1);
            }
        }
    }
}

// ---------------- pooled BN+ReLU finalize (also zeroes colsum buffer) ----------------
__global__ void __launch_bounds__(256) pool_finalize(float* __restrict__ xp,
                              const float* __restrict__ pmax, const float* __restrict__ pmin,
                              const double* __restrict__ bssum, const double* __restrict__ bssq,
                              const float* __restrict__ bg, const float* __restrict__ bbe,
                              float* __restrict__ colsum) {
    __shared__ float tf_s[128], tf_h[128];
    int tid = threadIdx.x;
    if (tid < 128) {
        double m = bssum[tid] / (double)P_TOT;
        double v = bssq[tid] / (double)P_TOT - m*m;
        float sc = bg[tid] * rsqrtf((float)v + EPSF);
        tf_s[tid] = sc;
        tf_h[tid] = bbe[tid] - (float)m * sc;
    }
    __syncthreads();
    int i = blockIdx.x*256 + tid;
    if (i < BB*NPT) colsum[i] = 0.f;
    if (i >= BB*128*NPT) return;
    int s = i & 511, c = (i >> 9) & 127, b = i >> 16;
    int src = c*(BB*NPT) + b*NPT + s;
    float sc = tf_s[c], sh = tf_h[c];
    float v = (sc >= 0.f) ? pmax[src] : pmin[src];
    xp[i] = fmaxf(fmaf(v, sc, sh), 0.f);
}

// ---------------- softmax rows (fast exp, fused column-sum atomics) ----------------
__global__ void __launch_bounds__(256) softmax_kernel(float* __restrict__ e,
                                                      float* __restrict__ colsum) {
    __shared__ float scol[NPT];
    int tid = threadIdx.x;
    int gw = (blockIdx.x*256 + tid) >> 5;         // row = blockIdx.x*8 + wid
    int lane = tid & 31;
    scol[tid] = 0.f;
    scol[tid + 256] = 0.f;
    __syncthreads();
    float* row = e + (long)gw * NPT;
    float v[16];
    float mx = -3.4e38f;
    #pragma unroll
    for (int i = 0; i < 16; ++i) { v[i] = row[lane + i*32]; mx = fmaxf(mx, v[i]); }
    #pragma unroll
    for (int off = 16; off > 0; off >>= 1)
        mx = fmaxf(mx, __shfl_xor_sync(0xFFFFFFFFu, mx, off));
    float sum = 0.f;
    #pragma unroll
    for (int i = 0; i < 16; ++i) { v[i] = __expf(v[i] - mx); sum += v[i]; }
    #pragma unroll
    for (int off = 16; off > 0; off >>= 1)
        sum += __shfl_xor_sync(0xFFFFFFFFu, sum, off);
    float inv = 1.f / sum;
    #pragma unroll
    for (int i = 0; i < 16; ++i) {
        float r = v[i] * inv;
        row[lane + i*32] = r;
        atomicAdd(&scol[lane + i*32], r);
    }
    __syncthreads();
    int b = blockIdx.x >> 6;                      // 64 blocks per batch
    atomicAdd(&colsum[b*NPT + tid], scol[tid]);
    atomicAdd(&colsum[b*NPT + tid + 256], scol[tid + 256]);
}

// ---------------- colsum -> reciprocal ----------------
__global__ void recip_kernel(float* __restrict__ c) {
    int i = blockIdx.x*256 + threadIdx.x;
    if (i < BB*NPT) c[i] = 1.f / (1e-9f + c[i]);
}

// ---------------- final residual (inline bn1d affine) ----------------
__global__ void __launch_bounds__(256) final_kernel(float* __restrict__ out,
                             const float* __restrict__ xp,
                             const float* __restrict__ y,
                             const double* __restrict__ bssum, const double* __restrict__ bssq,
                             const float* __restrict__ bg, const float* __restrict__ bbe,
                             const float* __restrict__ alpha, const float* __restrict__ beta) {
    __shared__ float tf_s[128], tf_h[128];
    int tid = threadIdx.x;
    if (tid < 128) {
        double m = bssum[tid] / (double)(BB*NPT);
        double v = bssq[tid] / (double)(BB*NPT) - m*m;
        float sc = bg[tid] * rsqrtf((float)v + EPSF);
        tf_s[tid] = sc;
        tf_h[tid] = bbe[tid] - (float)m * sc;
    }
    __syncthreads();
    int i = blockIdx.x*256 + tid;
    if (i >= BB*128*NPT) return;
    int c = (i >> 9) & 127;
    float xr = fmaxf(fmaf(y[i], tf_s[c], tf_h[c]), 0.f);
    out[i] = xp[i] + alpha[c]*xr + beta[c];
}

// ---------------- launch ----------------
extern "C" void kernel_launch(void* const* d_in, const int* in_sizes, int n_in,
                              void* d_out, int out_size) {
    const float* xyz    = (const float*)d_in[0];
    const float* points = (const float*)d_in[1];
    const float* w0 = (const float*)d_in[2];
    const float* b0 = (const float*)d_in[3];
    const float* g0 = (const float*)d_in[4];
    const float* be0= (const float*)d_in[5];
    const float* w1 = (const float*)d_in[6];
    const float* b1 = (const float*)d_in[7];
    const float* g1 = (const float*)d_in[8];
    const float* be1= (const float*)d_in[9];
    const float* w2 = (const float*)d_in[10];
    const float* b2 = (const float*)d_in[11];
    const float* g2 = (const float*)d_in[12];
    const float* be2= (const float*)d_in[13];
    const float* wl = (const float*)d_in[14];
    const float* bl = (const float*)d_in[15];
    const float* gl = (const float*)d_in[16];
    const float* bel= (const float*)d_in[17];
    const float* wv = (const float*)d_in[18];
    const float* bv = (const float*)d_in[19];
    const float* wt = (const float*)d_in[20];
    const float* bt = (const float*)d_in[21];
    const float* gn = (const float*)d_in[22];
    const float* gb = (const float*)d_in[23];
    const float* alpha = (const float*)d_in[24];
    const float* beta  = (const float*)d_in[25];
    float* out = (float*)d_out;

    float *xp, *x0, *energy, *x2, *y, *colrcp, *pmax, *pmin;
    __half *hA, *hB;
    double *ssum, *ssq;
    int *fps, *nbr;
    cudaGetSymbolAddress((void**)&hA, g_hA);
    cudaGetSymbolAddress((void**)&hB, g_hB);
    cudaGetSymbolAddress((void**)&xp, g_xp);
    cudaGetSymbolAddress((void**)&x0, g_x0);
    cudaGetSymbolAddress((void**)&energy, g_energy);
    cudaGetSymbolAddress((void**)&x2, g_x2);
    cudaGetSymbolAddress((void**)&y, g_y);
    cudaGetSymbolAddress((void**)&ssum, g_ssum);
    cudaGetSymbolAddress((void**)&ssq, g_ssq);
    cudaGetSymbolAddress((void**)&colrcp, g_colrcp);
    cudaGetSymbolAddress((void**)&pmax, g_pmax);
    cudaGetSymbolAddress((void**)&pmin, g_pmin);
    cudaGetSymbolAddress((void**)&fps, g_fps);
    cudaGetSymbolAddress((void**)&nbr, g_nbr);

    const int SMEM_PTS = 3*NN*sizeof(float);   // 48KB
    cudaFuncSetAttribute(fps_kernel,  cudaFuncAttributeMaxDynamicSharedMemorySize, 64*1024);
    cudaFuncSetAttribute(ball_kernel, cudaFuncAttributeMaxDynamicSharedMemorySize, 64*1024);

    const int SM_H64  = 2*(32*128 + 64*40) * 2;    // 26624
    const int SM_H128 = 2*(32*128 + 128*40) * 2;   // 36864
    const int SM_N128 = 32*136*4 + 128*36*4;       // 35840
    const int SM_N64  = 32*136*4 + 64*36*4;        // 26624

    // geometry (4th launch = L0 fp16 GEMM for ncu capture)
    fps_kernel<<<BB, 1024, SMEM_PTS>>>(xyz, fps);
    ball_kernel<<<dim3(NPT/16, BB), 512, SMEM_PTS>>>(xyz, fps, nbr);
    feat_kernel<<<dim3(NPT, BB), 256>>>(points, xyz, fps, nbr, hB, hA + 128L*P_TOT);

    // L0: 128->64, stats slot0
    gemm_h<64,false,true,false><<<P_TOT/128, 256, SM_H64>>>(
        w0, 128, hB, hA, b0, nullptr, nullptr, nullptr, nullptr, 0,
        ssum+0, ssq+0, nullptr, nullptr, 128);
    newxyz_kernel<<<(BB*3*NPT + 255)/256, 256>>>(out, xyz, fps);

    // L1: 64->64, xform from slot0 stats (g0/be0), stats slot1
    gemm_h<64,true,true,false><<<P_TOT/128, 256, SM_H64>>>(
        w1, 64, hA, hB, b1, ssum+0, ssq+0, g0, be0, 64,
        ssum+128, ssq+128, nullptr, nullptr, 64);

    // L2: 64->128, xform from slot1 (g1/be1), stats slot2
    gemm_h<128,true,true,false><<<P_TOT/128, 256, SM_H128>>>(
        w2, 64, hB, hA, b2, ssum+128, ssq+128, g1, be1, 64,
        ssum+256, ssq+256, nullptr, nullptr, 64);

    // Ll: 131->128, xform from slot2 (g2/be2, 128 BN + 3 pass), stats slot3, POOL
    gemm_h<128,true,true,true><<<P_TOT/128, 256, SM_H128>>>(
        wl, 131, hA, nullptr, bl, ssum+256, ssq+256, g2, be2, 128,
        ssum+384, ssq+384, pmax, pmin, 131);
    pool_finalize<<<(BB*128*NPT + 255)/256, 256>>>(xp, pmax, pmin,
        ssum+384, ssq+384, gl, bel, colrcp);

    // attention (tf32); wv/x2/wt split into COUT=64 tiles for 2x parallelism
    gemm_tc<64,false,false,false,false><<<dim3(NPT/128, BB, 2), 256, SM_N64>>>(
        wv, 128, 0, xp, nullptr, PB, nullptr, 0, x0, PB, bv,
        nullptr, nullptr, 128, NPT);
    gemm_tc<128,true,false,false,false><<<dim3(NPT/128, BB, 4), 256, SM_N128>>>(
        xp, NPT, PB, x0, nullptr, PB, nullptr, 0, energy, (long)NPT*NPT, nullptr,
        nullptr, nullptr, 128, NPT);
    softmax_kernel<<<(BB*NPT)/8, 256>>>(energy, colrcp);
    recip_kernel<<<(BB*NPT + 255)/256, 256>>>(colrcp);
    gemm_tc<64,false,false,true,false><<<dim3(NPT/128, BB, 2), 256, SM_N64>>>(
        x0, NPT, PB, energy, nullptr, (long)NPT*NPT, colrcp, NPT, x2, PB, nullptr,
        nullptr, nullptr, NPT, NPT);
    gemm_tc<64,false,true,false,true><<<dim3(NPT/128, BB, 2), 256, SM_N64>>>(
        wt, 128, 0, xp, x2, PB, nullptr, 0, y, PB, bt,
        ssum+512, ssq+512, 128, NPT);

    final_kernel<<<(BB*128*NPT + 255)/256, 256>>>(out + BB*3*NPT, xp, y,
        ssum+512, ssq+512, gn, gb, alpha, beta);
}

// round 16
// speedup vs baseline: 1.0372x; 1.0099x over previous
#include <cuda_runtime.h>
#include <cuda_bf16.h>
#include <cuda_fp16.h>
#include <cstdint>
#include <math.h>

// ---------------- constants ----------------
#define BB   16
#define NN   4096
#define DD   64
#define NPT  512
#define KK   32
#define P_TOT (BB*NPT*KK)     // 262144
#define PB   (128*NPT)        // 65536 per-batch (c,s) block
#define EPSF 1e-5f

// ---------------- scratch ----------------
__device__ __half g_hA[131L * P_TOT];           // 131 x P halves (rows 128..130 = rel_xyz)
__device__ __half g_hB[128L * P_TOT];           // 128 x P halves
__device__ float g_ptsT[(long)BB*NN*DD];        // points transposed [b][n][c]
__device__ float g_xp[BB*128*NPT];
__device__ float g_x0[BB*128*NPT];
__device__ float g_energy[BB*NPT*NPT];
__device__ float g_x2[BB*128*NPT];
__device__ float g_y[BB*128*NPT];
__device__ float g_pmax[128*BB*NPT];
__device__ float g_pmin[128*BB*NPT];
__device__ double g_ssum[5*128];
__device__ double g_ssq[5*128];
__device__ float g_colrcp[BB*NPT];
__device__ int   g_fps[BB*NPT];
__device__ int   g_nbr[BB*NPT*KK];

// ---------------- points transpose: [b][c][n] -> [b][n][c] (exact copy) ------
__global__ void __launch_bounds__(256) transpose_pts(const float* __restrict__ points,
                                                     float* __restrict__ ptsT) {
    __shared__ float t[64][65];
    int b = blockIdx.y, n0 = blockIdx.x*64, tid = threadIdx.x;
    int nl = tid & 63, cg = tid >> 6;           // cg 0..3
    #pragma unroll
    for (int cc = 0; cc < 16; ++cc) {
        int c = cg*16 + cc;
        t[nl][c] = points[(long)b*DD*NN + c*NN + n0 + nl];
    }
    __syncthreads();
    #pragma unroll
    for (int j = 0; j < 16; ++j) {
        int idx = tid + j*256;
        int n = idx >> 6, c = idx & 63;
        ptsT[((long)b*NN + n0 + n)*64 + c] = t[n][c];
    }
}

// ---------------- FPS (single barrier per iteration) ----------------
__global__ void __launch_bounds__(1024) fps_kernel(const float* __restrict__ xyz,
                                                   int* __restrict__ fps) {
    extern __shared__ char xsm[];
    float* sm = (float*)xsm;
    float* sx = sm;
    float* sy = sm + NN;
    float* sz = sm + 2*NN;
    __shared__ unsigned long long swarp[2][32];
    int b = blockIdx.x, tid = threadIdx.x;
    int lane = tid & 31, wid = tid >> 5;
    const float* base = xyz + (long)b*3*NN;
    for (int i = tid; i < NN; i += 1024) {
        sx[i] = base[i];
        sy[i] = base[NN + i];
        sz[i] = base[2*NN + i];
    }
    __syncthreads();
    float dist[4];
    dist[0] = dist[1] = dist[2] = dist[3] = 1e10f;
    int far = 0;
    for (int it = 0; it < NPT; ++it) {
        if (tid == 0) fps[b*NPT + it] = far;
        float cx = sx[far], cy = sy[far], cz = sz[far];
        unsigned long long best = 0ull;
        #pragma unroll
        for (int j = 0; j < 4; ++j) {
            int n = tid + j*1024;
            float dx = sx[n]-cx, dy = sy[n]-cy, dz = sz[n]-cz;
            float d = dx*dx + dy*dy + dz*dz;
            float dd = fminf(dist[j], d);
            dist[j] = dd;
            unsigned long long key =
                ((unsigned long long)__float_as_uint(dd) << 32) |
                (unsigned long long)(0xFFFFFFFFu - (unsigned)n);
            best = (key > best) ? key : best;
        }
        #pragma unroll
        for (int off = 16; off > 0; off >>= 1) {
            unsigned long long o = __shfl_xor_sync(0xFFFFFFFFu, best, off);
            best = (o > best) ? o : best;
        }
        if (lane == 0) swarp[it & 1][wid] = best;
        __syncthreads();
        best = swarp[it & 1][lane];
        #pragma unroll
        for (int off = 16; off > 0; off >>= 1) {
            unsigned long long o = __shfl_xor_sync(0xFFFFFFFFu, best, off);
            best = (o > best) ? o : best;
        }
        far = (int)(0xFFFFFFFFu - (unsigned)(best & 0xFFFFFFFFull));
    }
}

// ---------------- new_xyz output ----------------
__global__ void newxyz_kernel(float* __restrict__ out, const float* __restrict__ xyz,
                              const int* __restrict__ fps) {
    int i = blockIdx.x*256 + threadIdx.x;
    if (i >= BB*3*NPT) return;
    int s = i & 511;
    int c = (i >> 9) % 3;
    int b = i / (3*NPT);
    out[i] = xyz[(long)b*3*NN + c*NN + fps[b*NPT + s]];
}

// ---------------- ball query (512 threads, 16 centers/block) ----------------
__global__ void __launch_bounds__(512) ball_kernel(const float* __restrict__ xyz,
                                                   const int* __restrict__ fps,
                                                   int* __restrict__ nbr) {
    extern __shared__ char xsm[];
    float* sm = (float*)xsm;
    float* sx = sm;
    float* sy = sm + NN;
    float* sz = sm + 2*NN;
    __shared__ int snb[16][KK];
    int b = blockIdx.y, tid = threadIdx.x;
    const float* base = xyz + (long)b*3*NN;
    for (int i = tid; i < NN; i += 512) {
        sx[i] = base[i];
        sy[i] = base[NN + i];
        sz[i] = base[2*NN + i];
    }
    __syncthreads();
    int w = tid >> 5, lane = tid & 31;
    int s = blockIdx.x*16 + w;
    int fi = fps[b*NPT + s];
    float cx = sx[fi], cy = sy[fi], cz = sz[fi];
    float cn = cx*cx + cy*cy + cz*cz;
    const float R2 = (float)(0.4*0.4);
    int cnt = 0;
    for (int n0 = 0; n0 < NN && cnt < KK; n0 += 32) {
        int n = n0 + lane;
        float px = sx[n], py = sy[n], pz = sz[n];
        float pn = px*px + py*py + pz*pz;
        float dt = cx*px + cy*py + cz*pz;
        float sq = (cn + pn) - 2.0f*dt;
        bool in = !(sq > R2);
        unsigned m = __ballot_sync(0xFFFFFFFFu, in);
        int pos = cnt + __popc(m & ((1u << lane) - 1u));
        if (in && pos < KK) snb[w][pos] = n;
        cnt += __popc(m);
    }
    __syncwarp();
    int v = (lane < cnt) ? snb[w][lane] : snb[w][0];
    nbr[(b*NPT + s)*KK + lane] = v;
}

// ---------------- feature build (transposed gather; zeros BN stats) ----------
__global__ void __launch_bounds__(256) feat_kernel(const float* __restrict__ ptsT,
                                                   const float* __restrict__ xyz,
                                                   const int* __restrict__ fps,
                                                   const int* __restrict__ nbr,
                                                   __half* __restrict__ X0,
                                                   __half* __restrict__ relbuf) {
    int s = blockIdx.x, b = blockIdx.y, tid = threadIdx.x;
    if (s == 0 && b == 0) {
        for (int i = tid; i < 5*128; i += 256) { g_ssum[i] = 0.0; g_ssq[i] = 0.0; }
    }
    __shared__ int snb[KK];
    __shared__ float scen[DD];
    __shared__ float scxyz[3];
    int fi = fps[b*NPT + s];
    if (tid < KK) snb[tid] = nbr[(b*NPT + s)*KK + tid];
    if (tid >= 32 && tid < 32+DD) scen[tid-32] = ptsT[((long)b*NN + fi)*64 + (tid-32)];
    if (tid >= 96 && tid < 99)   scxyz[tid-96] = xyz[(long)b*3*NN + (tid-96)*NN + fi];
    __syncthreads();
    int k = tid & 31, cb = tid >> 5;
    int n = snb[k];
    int base = (b*NPT + s)*KK + k;
    const float4* pr = reinterpret_cast<const float4*>(&ptsT[((long)b*NN + n)*64 + cb*8]);
    float4 v0 = pr[0], v1 = pr[1];
    float pv[8] = {v0.x, v0.y, v0.z, v0.w, v1.x, v1.y, v1.z, v1.w};
    #pragma unroll
    for (int q = 0; q < 8; ++q) {
        int c = cb*8 + q;
        float v = pv[q];
        X0[(long)c*P_TOT + base] = __float2half(v);
        X0[(long)(DD+c)*P_TOT + base] = __float2half(v - scen[c]);
    }
    if (cb < 3) {
        float v = xyz[(long)b*3*NN + cb*NN + n] - scxyz[cb];
        relbuf[(long)cb*P_TOT + base] = __float2half(v);
    }
}

// ---------------- mma helpers ----------------
__device__ __forceinline__ uint32_t f2tf32(float v) {
    uint32_t r;
    asm("cvt.rna.tf32.f32 %0, %1;" : "=r"(r) : "f"(v));
    return r;
}
__device__ __forceinline__ void mma_tf32(float* d, uint32_t a0, uint32_t a1,
                                         uint32_t a2, uint32_t a3,
                                         uint32_t b0, uint32_t b1) {
    asm volatile("mma.sync.aligned.m16n8k8.row.col.f32.tf32.tf32.f32 "
        "{%0,%1,%2,%3},{%4,%5,%6,%7},{%8,%9},{%0,%1,%2,%3};"
        : "+f"(d[0]), "+f"(d[1]), "+f"(d[2]), "+f"(d[3])
        : "r"(a0), "r"(a1), "r"(a2), "r"(a3), "r"(b0), "r"(b1));
}
__device__ __forceinline__ void mma_f16(float* d, uint32_t a0, uint32_t a1,
                                        uint32_t a2, uint32_t a3,
                                        uint32_t b0, uint32_t b1) {
    asm volatile("mma.sync.aligned.m16n8k16.row.col.f32.f16.f16.f32 "
        "{%0,%1,%2,%3},{%4,%5,%6,%7},{%8,%9},{%0,%1,%2,%3};"
        : "+f"(d[0]), "+f"(d[1]), "+f"(d[2]), "+f"(d[3])
        : "r"(a0), "r"(a1), "r"(a2), "r"(a3), "r"(b0), "r"(b1));
}
__device__ __forceinline__ void ldsm_x4_trans(uint32_t& r0, uint32_t& r1,
                                              uint32_t& r2, uint32_t& r3, uint32_t addr) {
    asm volatile("ldmatrix.sync.aligned.m8n8.x4.trans.shared.b16 {%0,%1,%2,%3}, [%4];"
        : "=r"(r0), "=r"(r1), "=r"(r2), "=r"(r3) : "r"(addr));
}

// ================= fp16 big-layer GEMM (double-buffered, 1 sync/chunk) =========
template<int COUT, bool XFORM, bool STATS, bool POOL>
__global__ void __launch_bounds__(256, (COUT == 64) ? 3 : 2)
gemm_h(const float* __restrict__ A, int lda,
       const __half* __restrict__ X,
       __half* __restrict__ Y,
       const float* __restrict__ bias,
       const double* __restrict__ bssum, const double* __restrict__ bssq,
       const float* __restrict__ bg, const float* __restrict__ bbe, int Cbn,
       double* __restrict__ ssum, double* __restrict__ ssq,
       float* __restrict__ pmax, float* __restrict__ pmin,
       int Cin)
{
    constexpr int MW = COUT / 4;
    constexpr int MF = MW / 16;
    constexpr int NH2 = COUT / 16;
    constexpr int XTILE = 32*128;
    constexpr int WTILE = COUT*40;
    extern __shared__ char xsm[];
    __half* sXh = (__half*)xsm;
    __half* sWh = sXh + 2*XTILE;
    __shared__ float tf_s[132], tf_h[132], tf_l[132];

    int p0 = blockIdx.x * 128;
    int tid = threadIdx.x;
    int lane = tid & 31, wid = tid >> 5;
    int warpM = wid >> 1, warpN = wid & 1;
    int gid = lane >> 2, tig = lane & 3;

    if (XFORM) {
        for (int c = tid; c < Cin; c += 256) {
            if (c < Cbn) {
                double m = bssum[c] / (double)P_TOT;
                double v = bssq[c] / (double)P_TOT - m*m;
                float sc = bg[c] * rsqrtf((float)v + EPSF);
                tf_s[c] = sc;
                tf_h[c] = bbe[c] - (float)m * sc;
                tf_l[c] = 0.f;
            } else {
                tf_s[c] = 1.f;
                tf_h[c] = 0.f;
                tf_l[c] = -3.4e38f;
            }
        }
    }

    uint32_t sX_base0 = (uint32_t)__cvta_generic_to_shared(sXh);

    float d[MF][8][4];
    #pragma unroll
    for (int mf = 0; mf < MF; ++mf)
        #pragma unroll
        for (int nf = 0; nf < 8; ++nf)
            #pragma unroll
            for (int i = 0; i < 4; ++i) d[mf][nf][i] = 0.f;

    uint4 xr[2];
    float wsf[2*NH2];
    int nchunk = (Cin + 31) >> 5;

    auto loadXreg = [&](int k0c) {
        #pragma unroll
        for (int j = 0; j < 2; ++j) {
            int id = tid + j*256;
            int k = id >> 4, seg = id & 15;
            int kg = k0c + k;
            uint4 v = make_uint4(0u, 0u, 0u, 0u);
            if (kg < Cin)
                v = *reinterpret_cast<const uint4*>(&X[(long)kg*P_TOT + p0 + seg*8]);
            xr[j] = v;
        }
    };
    auto storeX = [&](int k0c, int buf) {
        __half* dst = sXh + buf*XTILE;
        #pragma unroll
        for (int j = 0; j < 2; ++j) {
            int id = tid + j*256;
            int k = id >> 4, seg = id & 15;
            uint4 v = xr[j];
            if (XFORM) {
                int kg = k0c + k;
                if (kg < Cin) {
                    float s = tf_s[kg], h = tf_h[kg], l = tf_l[kg];
                    uint32_t* w = &v.x;
                    #pragma unroll
                    for (int q = 0; q < 4; ++q) {
                        __half2 hv = *reinterpret_cast<__half2*>(&w[q]);
                        float f0 = __low2float(hv), f1 = __high2float(hv);
                        f0 = fmaxf(fmaf(f0, s, h), l);
                        f1 = fmaxf(fmaf(f1, s, h), l);
                        __half2 ho = __floats2half2_rn(f0, f1);
                        w[q] = *reinterpret_cast<uint32_t*>(&ho);
                    }
                }
            }
            int segp = seg ^ (k & 7);
            *reinterpret_cast<uint4*>(&dst[k*128 + segp*8]) = v;
        }
    };
    auto loadWreg = [&](int k0c) {
        #pragma unroll
        for (int j = 0; j < NH2; ++j) {
            int hid = tid + j*256;
            int co = hid >> 4, kp = hid & 15;
            int k = k0c + 2*kp;
            wsf[2*j]   = (k   < Cin) ? A[(long)co*lda + k]   : 0.f;
            wsf[2*j+1] = (k+1 < Cin) ? A[(long)co*lda + k+1] : 0.f;
        }
    };
    auto storeW = [&](int buf) {
        __half* dst = sWh + buf*WTILE;
        #pragma unroll
        for (int j = 0; j < NH2; ++j) {
            int hid = tid + j*256;
            int co = hid >> 4, kp = hid & 15;
            __half2 hp = __floats2half2_rn(wsf[2*j], wsf[2*j+1]);
            *reinterpret_cast<__half2*>(&dst[co*40 + 2*kp]) = hp;
        }
    };

    auto mmaPhase = [&](int buf) {
        const __half* sW = sWh + buf*WTILE;
        uint32_t sX_base = sX_base0 + (uint32_t)(buf*XTILE*2);
        int mi = lane >> 3, lr = lane & 7;
        #pragma unroll
        for (int g16 = 0; g16 < 32; g16 += 16) {
            uint32_t a[MF][4];
            #pragma unroll
            for (int mf = 0; mf < MF; ++mf) {
                int r = warpM*MW + mf*16 + gid;
                a[mf][0] = *reinterpret_cast<const uint32_t*>(&sW[r*40 + g16 + 2*tig]);
                a[mf][1] = *reinterpret_cast<const uint32_t*>(&sW[(r+8)*40 + g16 + 2*tig]);
                a[mf][2] = *reinterpret_cast<const uint32_t*>(&sW[r*40 + g16 + 2*tig + 8]);
                a[mf][3] = *reinterpret_cast<const uint32_t*>(&sW[(r+8)*40 + g16 + 2*tig + 8]);
            }
            int kl = g16 + ((mi & 1) << 3) + lr;
            #pragma unroll
            for (int np = 0; np < 4; ++np) {
                int seg = warpN*8 + np*2 + (mi >> 1);
                int segp = seg ^ (kl & 7);
                uint32_t addr = sX_base + (uint32_t)((kl*128 + segp*8) * 2);
                uint32_t b0, b1, b2, b3;
                ldsm_x4_trans(b0, b1, b2, b3, addr);
                #pragma unroll
                for (int mf = 0; mf < MF; ++mf) {
                    mma_f16(d[mf][2*np],   a[mf][0], a[mf][1], a[mf][2], a[mf][3], b0, b1);
                    mma_f16(d[mf][2*np+1], a[mf][0], a[mf][1], a[mf][2], a[mf][3], b2, b3);
                }
            }
        }
    };

    loadXreg(0);
    loadWreg(0);
    if (XFORM) __syncthreads();
    storeX(0, 0);
    storeW(0);
    __syncthreads();
    for (int c0 = 0; c0 < nchunk; ++c0) {
        int cur = c0 & 1;
        if (c0 + 1 < nchunk) { loadXreg((c0+1)*32); loadWreg((c0+1)*32); }
        mmaPhase(cur);
        if (c0 + 1 < nchunk) {
            storeX((c0+1)*32, 1 - cur);
            storeW(1 - cur);
            __syncthreads();
        }
    }

    // epilogue
    #pragma unroll
    for (int mf = 0; mf < MF; ++mf) {
        int r = warpM*MW + mf*16 + gid;
        int co0 = r, co1 = r + 8;
        float bb0 = bias ? bias[co0] : 0.f;
        float bb1 = bias ? bias[co1] : 0.f;
        double s0 = 0.0, q0 = 0.0, s1 = 0.0, q1 = 0.0;
        float mxa[2], mna[2], mxb[2], mnb[2];
        if (POOL) {
            mxa[0] = mxa[1] = mxb[0] = mxb[1] = -3.4e38f;
            mna[0] = mna[1] = mnb[0] = mnb[1] =  3.4e38f;
        }
        #pragma unroll
        for (int nf = 0; nf < 8; ++nf) {
            int p = p0 + warpN*64 + nf*8 + 2*tig;
            float o0 = d[mf][nf][0] + bb0, o1 = d[mf][nf][1] + bb0;
            float o2 = d[mf][nf][2] + bb1, o3 = d[mf][nf][3] + bb1;
            if (!POOL) {
                *reinterpret_cast<__half2*>(&Y[(long)co0*P_TOT + p]) = __floats2half2_rn(o0, o1);
                *reinterpret_cast<__half2*>(&Y[(long)co1*P_TOT + p]) = __floats2half2_rn(o2, o3);
            } else {
                int g = nf >> 2;
                mxa[g] = fmaxf(mxa[g], fmaxf(o0, o1));
                mna[g] = fminf(mna[g], fminf(o0, o1));
                mxb[g] = fmaxf(mxb[g], fmaxf(o2, o3));
                mnb[g] = fminf(mnb[g], fminf(o2, o3));
            }
            if (STATS) {
                s0 += (double)o0 + (double)o1;
                q0 += (double)o0*o0 + (double)o1*o1;
                s1 += (double)o2 + (double)o3;
                q1 += (double)o2*o2 + (double)o3*o3;
            }
        }
        if (POOL) {
            const int PS = P_TOT >> 5;
            #pragma unroll
            for (int g = 0; g < 2; ++g) {
                float ma = mxa[g], na = mna[g], mb = mxb[g], nb = mnb[g];
                #pragma unroll
                for (int off = 1; off <= 2; off <<= 1) {
                    ma = fmaxf(ma, __shfl_xor_sync(0xFFFFFFFFu, ma, off));
                    na = fminf(na, __shfl_xor_sync(0xFFFFFFFFu, na, off));
                    mb = fmaxf(mb, __shfl_xor_sync(0xFFFFFFFFu, mb, off));
                    nb = fminf(nb, __shfl_xor_sync(0xFFFFFFFFu, nb, off));
                }
                if (tig == 0) {
                    int ps = (p0 >> 5) + warpN*2 + g;
                    pmax[(long)co0*PS + ps] = ma;
                    pmin[(long)co0*PS + ps] = na;
                    pmax[(long)co1*PS + ps] = mb;
                    pmin[(long)co1*PS + ps] = nb;
                }
            }
        }
        if (STATS) {
            #pragma unroll
            for (int off = 1; off <= 2; off <<= 1) {
                s0 += __shfl_xor_sync(0xFFFFFFFFu, s0, off);
                q0 += __shfl_xor_sync(0xFFFFFFFFu, q0, off);
                s1 += __shfl_xor_sync(0xFFFFFFFFu, s1, off);
                q1 += __shfl_xor_sync(0xFFFFFFFFu, q1, off);
            }
            if (tig == 0) {
                atomicAdd(&ssum[co0], s0);
                atomicAdd(&ssq[co0], q0);
                atomicAdd(&ssum[co1], s1);
                atomicAdd(&ssq[co1], q1);
            }
        }
    }
}

// ================= fp32/tf32 GEMM (attention; single-buffer) =================
// PSCALE: per-column scale = 1/(1e-9 + pscale[p]) precomputed per block in smem.
template<int COUT, bool TRANSA, bool SUB, bool PSCALE, bool STATS>
__global__ void __launch_bounds__(256)
gemm_tc(const float* __restrict__ A, int lda, long aStride,
        const float* __restrict__ X, const float* __restrict__ X2, long xStride,
        const float* __restrict__ pscale, int psStride,
        float* __restrict__ Y, long yStride,
        const float* __restrict__ bias,
        double* __restrict__ ssum, double* __restrict__ ssq,
        int Cin, int P)
{
    constexpr int MW = COUT / 4;
    constexpr int MF = MW / 16;
    constexpr int NW = (COUT*32)/256;
    extern __shared__ char xsm[];
    uint32_t* sX = (uint32_t*)xsm;              // 32*136
    uint32_t* sW = sX + 32*136;                 // COUT*36
    __shared__ float spsc[128];

    int by = blockIdx.y;
    A += (long)by * aStride;
    X += (long)by * xStride;
    if (SUB) X2 += (long)by * xStride;
    Y += (long)by * yStride;
    int coBase = blockIdx.z * COUT;
    int p0 = blockIdx.x * 128;

    int tid = threadIdx.x;
    int lane = tid & 31, wid = tid >> 5;
    int warpM = wid >> 1, warpN = wid & 1;
    int gid = lane >> 2, tig = lane & 3;

    if (PSCALE) {
        if (tid < 128)
            spsc[tid] = 1.f / (1e-9f + pscale[(long)by*psStride + p0 + tid]);
    }

    float d[MF][8][4];
    #pragma unroll
    for (int mf = 0; mf < MF; ++mf)
        #pragma unroll
        for (int nf = 0; nf < 8; ++nf)
            #pragma unroll
            for (int i = 0; i < 4; ++i) d[mf][nf][i] = 0.f;

    uint32_t xs[16];
    uint32_t ws[NW];
    int nchunk = (Cin + 31) >> 5;

    auto loadX_g = [&](int k0) {
        #pragma unroll
        for (int j = 0; j < 4; ++j) {
            int id = tid + j*256;
            int row = id >> 5, c4 = id & 31;
            int k = k0 + row;
            float4 v = make_float4(0.f, 0.f, 0.f, 0.f);
            if (k < Cin) {
                v = *reinterpret_cast<const float4*>(&X[(long)k*P + p0 + c4*4]);
                if (SUB) {
                    float4 u = *reinterpret_cast<const float4*>(&X2[(long)k*P + p0 + c4*4]);
                    v.x -= u.x; v.y -= u.y; v.z -= u.z; v.w -= u.w;
                }
                if (PSCALE) {
                    v.x *= spsc[c4*4+0]; v.y *= spsc[c4*4+1];
                    v.z *= spsc[c4*4+2]; v.w *= spsc[c4*4+3];
                }
            }
            xs[j*4+0] = f2tf32(v.x); xs[j*4+1] = f2tf32(v.y);
            xs[j*4+2] = f2tf32(v.z); xs[j*4+3] = f2tf32(v.w);
        }
    };
    auto loadW = [&](int k0) {
        #pragma unroll
        for (int j = 0; j < NW; ++j) {
            int id = tid + j*256;
            int co = id >> 5, kk = id & 31;
            int k = k0 + kk;
            float w = 0.f;
            if (k < Cin)
                w = TRANSA ? A[(long)k*lda + coBase + co]
                           : A[(long)(coBase + co)*lda + k];
            ws[j] = f2tf32(w);
        }
    };
    auto storeTiles = [&]() {
        #pragma unroll
        for (int j = 0; j < 4; ++j) {
            int id = tid + j*256;
            int row = id >> 5, c4 = id & 31;
            *reinterpret_cast<uint4*>(sX + row*136 + c4*4) =
                make_uint4(xs[j*4], xs[j*4+1], xs[j*4+2], xs[j*4+3]);
        }
        #pragma unroll
        for (int j = 0; j < NW; ++j) {
            int id = tid + j*256;
            int co = id >> 5, kk = id & 31;
            sW[co*36 + kk] = ws[j];
        }
    };
    auto mmaPhase = [&]() {
        #pragma unroll
        for (int k8 = 0; k8 < 4; ++k8) {
            int kb = k8*8;
            uint32_t a[MF][4];
            #pragma unroll
            for (int mf = 0; mf < MF; ++mf) {
                int r = warpM*MW + mf*16 + gid;
                a[mf][0] = sW[r*36 + kb + tig];
                a[mf][1] = sW[(r+8)*36 + kb + tig];
                a[mf][2] = sW[r*36 + kb + tig + 4];
                a[mf][3] = sW[(r+8)*36 + kb + tig + 4];
            }
            #pragma unroll
            for (int nf = 0; nf < 8; ++nf) {
                int col = warpN*64 + nf*8 + gid;
                uint32_t b0 = sX[(kb + tig)*136 + col];
                uint32_t b1 = sX[(kb + tig + 4)*136 + col];
                #pragma unroll
                for (int mf = 0; mf < MF; ++mf)
                    mma_tf32(d[mf][nf], a[mf][0], a[mf][1], a[mf][2], a[mf][3], b0, b1);
            }
        }
    };

    if (PSCALE) __syncthreads();        // spsc visible before loadX_g
    loadX_g(0);
    loadW(0);
    for (int c0 = 0; c0 < nchunk; ++c0) {
        storeTiles();
        __syncthreads();
        if (c0 + 1 < nchunk) { loadX_g((c0+1)*32); loadW((c0+1)*32); }
        mmaPhase();
        __syncthreads();
    }

    #pragma unroll
    for (int mf = 0; mf < MF; ++mf) {
        int r = warpM*MW + mf*16 + gid;
        int co0 = coBase + r, co1 = co0 + 8;
        float bb0 = bias ? bias[co0] : 0.f;
        float bb1 = bias ? bias[co1] : 0.f;
        double s0 = 0.0, q0 = 0.0, s1 = 0.0, q1 = 0.0;
        #pragma unroll
        for (int nf = 0; nf < 8; ++nf) {
            int p = p0 + warpN*64 + nf*8 + 2*tig;
            float o0 = d[mf][nf][0] + bb0, o1 = d[mf][nf][1] + bb0;
            float o2 = d[mf][nf][2] + bb1, o3 = d[mf][nf][3] + bb1;
            *reinterpret_cast<float2*>(&Y[(long)co0*P + p]) = make_float2(o0, o1);
            *reinterpret_cast<float2*>(&Y[(long)co1*P + p]) = make_float2(o2, o3);
            if (STATS) {
                s0 += (double)o0 + (double)o1;
                q0 += (double)o0*o0 + (double)o1*o1;
                s1 += (double)o2 + (double)o3;
                q1 += (double)o2*o2 + (double)o3*o3;
            }
        }
        if (STATS) {
            #pragma unroll
            for (int off = 1; off <= 2; off <<= 1) {
                s0 += __shfl_xor_sync(0xFFFFFFFFu, s0, off);
                q0 += __shfl_xor_sync(0xFFFFFFFFu, q0, off);
                s1 += __shfl_xor_sync(0xFFFFFFFFu, s1, off);
                q1 += __shfl_xor_sync(0xFFFFFFFFu, q1, off);
            }
            if (tig == 0) {
                atomicAdd(&ssum[co0], s0);
                atomicAdd(&ssq[co0], q0);
                atomicAdd(&ssum[co1], s1);
                atomicAdd(&ssq[co1], q1);
            }
        }
    }
}

// ---------------- pooled BN+ReLU finalize (also zeroes colsum buffer) ----------------
__global__ void __launch_bounds__(256) pool_finalize(float* __restrict__ xp,
                              const float* __restrict__ pmax, const float* __restrict__ pmin,
                              const double* __restrict__ bssum, const double* __restrict__ bssq,
                              const float* __restrict__ bg, const float* __restrict__ bbe,
                              float* __restrict__ colsum) {
    __shared__ float tf_s[128], tf_h[128];
    int tid = threadIdx.x;
    if (tid < 128) {
        double m = bssum[tid] / (double)P_TOT;
        double v = bssq[tid] / (double)P_TOT - m*m;
        float sc = bg[tid] * rsqrtf((float)v + EPSF);
        tf_s[tid] = sc;
        tf_h[tid] = bbe[tid] - (float)m * sc;
    }
    __syncthreads();
    int i = blockIdx.x*256 + tid;
    if (i < BB*NPT) colsum[i] = 0.f;
    if (i >= BB*128*NPT) return;
    int s = i & 511, c = (i >> 9) & 127, b = i >> 16;
    int src = c*(BB*NPT) + b*NPT + s;
    float sc = tf_s[c], sh = tf_h[c];
    float v = (sc >= 0.f) ? pmax[src] : pmin[src];
    xp[i] = fmaxf(fmaf(v, sc, sh), 0.f);
}

// ---------------- softmax rows (fast exp, fused column-sum atomics) ----------------
__global__ void __launch_bounds__(256) softmax_kernel(float* __restrict__ e,
                                                      float* __restrict__ colsum) {
    __shared__ float scol[NPT];
    int tid = threadIdx.x;
    int gw = (blockIdx.x*256 + tid) >> 5;
    int lane = tid & 31;
    scol[tid] = 0.f;
    scol[tid + 256] = 0.f;
    __syncthreads();
    float* row = e + (long)gw * NPT;
    float v[16];
    float mx = -3.4e38f;
    #pragma unroll
    for (int i = 0; i < 16; ++i) { v[i] = row[lane + i*32]; mx = fmaxf(mx, v[i]); }
    #pragma unroll
    for (int off = 16; off > 0; off >>= 1)
        mx = fmaxf(mx, __shfl_xor_sync(0xFFFFFFFFu, mx, off));
    float sum = 0.f;
    #pragma unroll
    for (int i = 0; i < 16; ++i) { v[i] = __expf(v[i] - mx); sum += v[i]; }
    #pragma unroll
    for (int off = 16; off > 0; off >>= 1)
        sum += __shfl_xor_sync(0xFFFFFFFFu, sum, off);
    float inv = 1.f / sum;
    #pragma unroll
    for (int i = 0; i < 16; ++i) {
        float r = v[i] * inv;
        row[lane + i*32] = r;
        atomicAdd(&scol[lane + i*32], r);
    }
    __syncthreads();
    int b = blockIdx.x >> 6;
    atomicAdd(&colsum[b*NPT + tid], scol[tid]);
    atomicAdd(&colsum[b*NPT + tid + 256], scol[tid + 256]);
}

// ---------------- final residual (inline bn1d affine) ----------------
__global__ void __launch_bounds__(256) final_kernel(float* __restrict__ out,
                             const float* __restrict__ xp,
                             const float* __restrict__ y,
                             const double* __restrict__ bssum, const double* __restrict__ bssq,
                             const float* __restrict__ bg, const float* __restrict__ bbe,
                             const float* __restrict__ alpha, const float* __restrict__ beta) {
    __shared__ float tf_s[128], tf_h[128];
    int tid = threadIdx.x;
    if (tid < 128) {
        double m = bssum[tid] / (double)(BB*NPT);
        double v = bssq[tid] / (double)(BB*NPT) - m*m;
        float sc = bg[tid] * rsqrtf((float)v + EPSF);
        tf_s[tid] = sc;
        tf_h[tid] = bbe[tid] - (float)m * sc;
    }
    __syncthreads();
    int i = blockIdx.x*256 + tid;
    if (i >= BB*128*NPT) return;
    int c = (i >> 9) & 127;
    float xr = fmaxf(fmaf(y[i], tf_s[c], tf_h[c]), 0.f);
    out[i] = xp[i] + alpha[c]*xr + beta[c];
}

// ---------------- launch ----------------
extern "C" void kernel_launch(void* const* d_in, const int* in_sizes, int n_in,
                              void* d_out, int out_size) {
    const float* xyz    = (const float*)d_in[0];
    const float* points = (const float*)d_in[1];
    const float* w0 = (const float*)d_in[2];
    const float* b0 = (const float*)d_in[3];
    const float* g0 = (const float*)d_in[4];
    const float* be0= (const float*)d_in[5];
    const float* w1 = (const float*)d_in[6];
    const float* b1 = (const float*)d_in[7];
    const float* g1 = (const float*)d_in[8];
    const float* be1= (const float*)d_in[9];
    const float* w2 = (const float*)d_in[10];
    const float* b2 = (const float*)d_in[11];
    const float* g2 = (const float*)d_in[12];
    const float* be2= (const float*)d_in[13];
    const float* wl = (const float*)d_in[14];
    const float* bl = (const float*)d_in[15];
    const float* gl = (const float*)d_in[16];
    const float* bel= (const float*)d_in[17];
    const float* wv = (const float*)d_in[18];
    const float* bv = (const float*)d_in[19];
    const float* wt = (const float*)d_in[20];
    const float* bt = (const float*)d_in[21];
    const float* gn = (const float*)d_in[22];
    const float* gb = (const float*)d_in[23];
    const float* alpha = (const float*)d_in[24];
    const float* beta  = (const float*)d_in[25];
    float* out = (float*)d_out;

    float *xp, *x0, *energy, *x2, *y, *colrcp, *pmax, *pmin, *ptsT;
    __half *hA, *hB;
    double *ssum, *ssq;
    int *fps, *nbr;
    cudaGetSymbolAddress((void**)&hA, g_hA);
    cudaGetSymbolAddress((void**)&hB, g_hB);
    cudaGetSymbolAddress((void**)&ptsT, g_ptsT);
    cudaGetSymbolAddress((void**)&xp, g_xp);
    cudaGetSymbolAddress((void**)&x0, g_x0);
    cudaGetSymbolAddress((void**)&energy, g_energy);
    cudaGetSymbolAddress((void**)&x2, g_x2);
    cudaGetSymbolAddress((void**)&y, g_y);
    cudaGetSymbolAddress((void**)&ssum, g_ssum);
    cudaGetSymbolAddress((void**)&ssq, g_ssq);
    cudaGetSymbolAddress((void**)&colrcp, g_colrcp);
    cudaGetSymbolAddress((void**)&pmax, g_pmax);
    cudaGetSymbolAddress((void**)&pmin, g_pmin);
    cudaGetSymbolAddress((void**)&fps, g_fps);
    cudaGetSymbolAddress((void**)&nbr, g_nbr);

    const int SMEM_PTS = 3*NN*sizeof(float);   // 48KB
    cudaFuncSetAttribute(fps_kernel,  cudaFuncAttributeMaxDynamicSharedMemorySize, 64*1024);
    cudaFuncSetAttribute(ball_kernel, cudaFuncAttributeMaxDynamicSharedMemorySize, 64*1024);

    const int SM_H64  = 2*(32*128 + 64*40) * 2;    // 26624
    const int SM_H128 = 2*(32*128 + 128*40) * 2;   // 36864
    const int SM_N128 = 32*136*4 + 128*36*4;       // 35840
    const int SM_N64  = 32*136*4 + 64*36*4;        // 26624

    // geometry (4th launch = feat_kernel for ncu verification of the gather rework)
    transpose_pts<<<dim3(NN/64, BB), 256>>>(points, ptsT);
    fps_kernel<<<BB, 1024, SMEM_PTS>>>(xyz, fps);
    ball_kernel<<<dim3(NPT/16, BB), 512, SMEM_PTS>>>(xyz, fps, nbr);
    feat_kernel<<<dim3(NPT, BB), 256>>>(ptsT, xyz, fps, nbr, hB, hA + 128L*P_TOT);

    // L0: 128->64, stats slot0
    gemm_h<64,false,true,false><<<P_TOT/128, 256, SM_H64>>>(
        w0, 128, hB, hA, b0, nullptr, nullptr, nullptr, nullptr, 0,
        ssum+0, ssq+0, nullptr, nullptr, 128);
    newxyz_kernel<<<(BB*3*NPT + 255)/256, 256>>>(out, xyz, fps);

    // L1: 64->64, xform from slot0 stats (g0/be0), stats slot1
    gemm_h<64,true,true,false><<<P_TOT/128, 256, SM_H64>>>(
        w1, 64, hA, hB, b1, ssum+0, ssq+0, g0, be0, 64,
        ssum+128, ssq+128, nullptr, nullptr, 64);

    // L2: 64->128, xform from slot1 (g1/be1), stats slot2
    gemm_h<128,true,true,false><<<P_TOT/128, 256, SM_H128>>>(
        w2, 64, hB, hA, b2, ssum+128, ssq+128, g1, be1, 64,
        ssum+256, ssq+256, nullptr, nullptr, 64);

    // Ll: 131->128, xform from slot2 (g2/be2, 128 BN + 3 pass), stats slot3, POOL
    gemm_h<128,true,true,true><<<P_TOT/128, 256, SM_H128>>>(
        wl, 131, hA, nullptr, bl, ssum+256, ssq+256, g2, be2, 128,
        ssum+384, ssq+384, pmax, pmin, 131);
    pool_finalize<<<(BB*128*NPT + 255)/256, 256>>>(xp, pmax, pmin,
        ssum+384, ssq+384, gl, bel, colrcp);

    // attention (tf32); wv/x2/wt split into COUT=64 tiles for 2x parallelism
    gemm_tc<64,false,false,false,false><<<dim3(NPT/128, BB, 2), 256, SM_N64>>>(
        wv, 128, 0, xp, nullptr, PB, nullptr, 0, x0, PB, bv,
        nullptr, nullptr, 128, NPT);
    gemm_tc<128,true,false,false,false><<<dim3(NPT/128, BB, 4), 256, SM_N128>>>(
        xp, NPT, PB, x0, nullptr, PB, nullptr, 0, energy, (long)NPT*NPT, nullptr,
        nullptr, nullptr, 128, NPT);
    softmax_kernel<<<(BB*NPT)/8, 256>>>(energy, colrcp);
    // x2 = x0 @ attn (column renorm: reciprocal computed in-kernel from colsum)
    gemm_tc<64,false,false,true,false><<<dim3(NPT/128, BB, 2), 256, SM_N64>>>(
        x0, NPT, PB, energy, nullptr, (long)NPT*NPT, colrcp, NPT, x2, PB, nullptr,
        nullptr, nullptr, NPT, NPT);
    gemm_tc<64,false,true,false,true><<<dim3(NPT/128, BB, 2), 256, SM_N64>>>(
        wt, 128, 0, xp, x2, PB, nullptr, 0, y, PB, bt,
        ssum+512, ssq+512, 128, NPT);

    final_kernel<<<(BB*128*NPT + 255)/256, 256>>>(out + BB*3*NPT, xp, y,
        ssum+512, ssq+512, gn, gb, alpha, beta);
}

// round 17
// speedup vs baseline: 1.2478x; 1.2030x over previous
#include <cuda_runtime.h>
#include <cuda_bf16.h>
#include <cuda_fp16.h>
#include <cstdint>
#include <math.h>

// ---------------- constants ----------------
#define BB   16
#define NN   4096
#define DD   64
#define NPT  512
#define KK   32
#define P_TOT (BB*NPT*KK)     // 262144
#define PB   (128*NPT)        // 65536 per-batch (c,s) block
#define EPSF 1e-5f

// ---------------- scratch ----------------
__device__ __half g_hA[131L * P_TOT];           // 131 x P halves (rows 128..130 = rel_xyz)
__device__ __half g_hB[128L * P_TOT];           // 128 x P halves
__device__ float g_ptsT[(long)BB*NN*DD];        // points transposed [b][n][c]
__device__ float g_xp[BB*128*NPT];
__device__ float g_x0[BB*128*NPT];
__device__ float g_energy[BB*NPT*NPT];
__device__ float g_x2[BB*128*NPT];
__device__ float g_y[BB*128*NPT];
__device__ float g_pmax[128*BB*NPT];
__device__ float g_pmin[128*BB*NPT];
__device__ double g_ssum[5*128];
__device__ double g_ssq[5*128];
__device__ float g_colrcp[BB*NPT];
__device__ int   g_fps[BB*NPT];
__device__ int   g_nbr[BB*NPT*KK];

// ---------------- points transpose: [b][c][n] -> [b][n][c] (exact copy) ------
__global__ void __launch_bounds__(256) transpose_pts(const float* __restrict__ points,
                                                     float* __restrict__ ptsT) {
    __shared__ float t[64][65];
    int b = blockIdx.y, n0 = blockIdx.x*64, tid = threadIdx.x;
    int nl = tid & 63, cg = tid >> 6;           // cg 0..3
    #pragma unroll
    for (int cc = 0; cc < 16; ++cc) {
        int c = cg*16 + cc;
        t[nl][c] = points[(long)b*DD*NN + c*NN + n0 + nl];
    }
    __syncthreads();
    #pragma unroll
    for (int j = 0; j < 16; ++j) {
        int idx = tid + j*256;
        int n = idx >> 6, c = idx & 63;
        ptsT[((long)b*NN + n0 + n)*64 + c] = t[n][c];
    }
}

// ---------------- FPS (REDUX reductions, single barrier per iteration) -------
__global__ void __launch_bounds__(1024) fps_kernel(const float* __restrict__ xyz,
                                                   int* __restrict__ fps) {
    extern __shared__ char xsm[];
    float* sm = (float*)xsm;
    float* sx = sm;
    float* sy = sm + NN;
    float* sz = sm + 2*NN;
    __shared__ unsigned long long swarp[2][32];
    int b = blockIdx.x, tid = threadIdx.x;
    int lane = tid & 31, wid = tid >> 5;
    const float* base = xyz + (long)b*3*NN;
    for (int i = tid; i < NN; i += 1024) {
        sx[i] = base[i];
        sy[i] = base[NN + i];
        sz[i] = base[2*NN + i];
    }
    __syncthreads();
    float dist[4];
    dist[0] = dist[1] = dist[2] = dist[3] = 1e10f;
    int far = 0;
    for (int it = 0; it < NPT; ++it) {
        if (tid == 0) fps[b*NPT + it] = far;
        float cx = sx[far], cy = sy[far], cz = sz[far];
        float bestd = -1.f;
        int bestn = 0;
        #pragma unroll
        for (int j = 0; j < 4; ++j) {
            int n = tid + j*1024;
            float dx = sx[n]-cx, dy = sy[n]-cy, dz = sz[n]-cz;
            float d = dx*dx + dy*dy + dz*dz;
            float dd = fminf(dist[j], d);
            dist[j] = dd;
            if (dd > bestd) { bestd = dd; bestn = n; }   // ascending n keeps lowest tie
        }
        unsigned db = __float_as_uint(bestd);            // >=0 floats: order-preserving
        unsigned maxd = __reduce_max_sync(0xFFFFFFFFu, db);
        int cand = (db == maxd) ? bestn : 0x7FFFFFFF;
        int minn = __reduce_min_sync(0xFFFFFFFFu, cand);
        if (lane == 0)
            swarp[it & 1][wid] = ((unsigned long long)maxd << 32) | (unsigned)minn;
        __syncthreads();
        unsigned long long v = swarp[it & 1][lane];
        unsigned db2 = (unsigned)(v >> 32);
        int n2 = (int)(v & 0xFFFFFFFFull);
        unsigned maxd2 = __reduce_max_sync(0xFFFFFFFFu, db2);
        int cand2 = (db2 == maxd2) ? n2 : 0x7FFFFFFF;
        far = __reduce_min_sync(0xFFFFFFFFu, cand2);
    }
}

// ---------------- new_xyz output ----------------
__global__ void newxyz_kernel(float* __restrict__ out, const float* __restrict__ xyz,
                              const int* __restrict__ fps) {
    int i = blockIdx.x*256 + threadIdx.x;
    if (i >= BB*3*NPT) return;
    int s = i & 511;
    int c = (i >> 9) % 3;
    int b = i / (3*NPT);
    out[i] = xyz[(long)b*3*NN + c*NN + fps[b*NPT + s]];
}

// ---------------- ball query (512 threads, 16 centers/block) ----------------
__global__ void __launch_bounds__(512) ball_kernel(const float* __restrict__ xyz,
                                                   const int* __restrict__ fps,
                                                   int* __restrict__ nbr) {
    extern __shared__ char xsm[];
    float* sm = (float*)xsm;
    float* sx = sm;
    float* sy = sm + NN;
    float* sz = sm + 2*NN;
    __shared__ int snb[16][KK];
    int b = blockIdx.y, tid = threadIdx.x;
    const float* base = xyz + (long)b*3*NN;
    for (int i = tid; i < NN; i += 512) {
        sx[i] = base[i];
        sy[i] = base[NN + i];
        sz[i] = base[2*NN + i];
    }
    __syncthreads();
    int w = tid >> 5, lane = tid & 31;
    int s = blockIdx.x*16 + w;
    int fi = fps[b*NPT + s];
    float cx = sx[fi], cy = sy[fi], cz = sz[fi];
    float cn = cx*cx + cy*cy + cz*cz;
    const float R2 = (float)(0.4*0.4);
    int cnt = 0;
    for (int n0 = 0; n0 < NN && cnt < KK; n0 += 32) {
        int n = n0 + lane;
        float px = sx[n], py = sy[n], pz = sz[n];
        float pn = px*px + py*py + pz*pz;
        float dt = cx*px + cy*py + cz*pz;
        float sq = (cn + pn) - 2.0f*dt;
        bool in = !(sq > R2);
        unsigned m = __ballot_sync(0xFFFFFFFFu, in);
        int pos = cnt + __popc(m & ((1u << lane) - 1u));
        if (in && pos < KK) snb[w][pos] = n;
        cnt += __popc(m);
    }
    __syncwarp();
    int v = (lane < cnt) ? snb[w][lane] : snb[w][0];
    nbr[(b*NPT + s)*KK + lane] = v;
}

// ---------------- feature build (transposed gather; zeros BN stats) ----------
__global__ void __launch_bounds__(256) feat_kernel(const float* __restrict__ ptsT,
                                                   const float* __restrict__ xyz,
                                                   const int* __restrict__ fps,
                                                   const int* __restrict__ nbr,
                                                   __half* __restrict__ X0,
                                                   __half* __restrict__ relbuf) {
    int s = blockIdx.x, b = blockIdx.y, tid = threadIdx.x;
    if (s == 0 && b == 0) {
        for (int i = tid; i < 5*128; i += 256) { g_ssum[i] = 0.0; g_ssq[i] = 0.0; }
    }
    __shared__ int snb[KK];
    __shared__ float scen[DD];
    __shared__ float scxyz[3];
    int fi = fps[b*NPT + s];
    if (tid < KK) snb[tid] = nbr[(b*NPT + s)*KK + tid];
    if (tid >= 32 && tid < 32+DD) scen[tid-32] = ptsT[((long)b*NN + fi)*64 + (tid-32)];
    if (tid >= 96 && tid < 99)   scxyz[tid-96] = xyz[(long)b*3*NN + (tid-96)*NN + fi];
    __syncthreads();
    int k = tid & 31, cb = tid >> 5;
    int n = snb[k];
    int base = (b*NPT + s)*KK + k;
    const float4* pr = reinterpret_cast<const float4*>(&ptsT[((long)b*NN + n)*64 + cb*8]);
    float4 v0 = pr[0], v1 = pr[1];
    float pv[8] = {v0.x, v0.y, v0.z, v0.w, v1.x, v1.y, v1.z, v1.w};
    #pragma unroll
    for (int q = 0; q < 8; ++q) {
        int c = cb*8 + q;
        float v = pv[q];
        X0[(long)c*P_TOT + base] = __float2half(v);
        X0[(long)(DD+c)*P_TOT + base] = __float2half(v - scen[c]);
    }
    if (cb < 3) {
        float v = xyz[(long)b*3*NN + cb*NN + n] - scxyz[cb];
        relbuf[(long)cb*P_TOT + base] = __float2half(v);
    }
}

// ---------------- mma helpers ----------------
__device__ __forceinline__ uint32_t f2tf32(float v) {
    uint32_t r;
    asm("cvt.rna.tf32.f32 %0, %1;" : "=r"(r) : "f"(v));
    return r;
}
__device__ __forceinline__ void mma_tf32(float* d, uint32_t a0, uint32_t a1,
                                         uint32_t a2, uint32_t a3,
                                         uint32_t b0, uint32_t b1) {
    asm volatile("mma.sync.aligned.m16n8k8.row.col.f32.tf32.tf32.f32 "
        "{%0,%1,%2,%3},{%4,%5,%6,%7},{%8,%9},{%0,%1,%2,%3};"
        : "+f"(d[0]), "+f"(d[1]), "+f"(d[2]), "+f"(d[3])
        : "r"(a0), "r"(a1), "r"(a2), "r"(a3), "r"(b0), "r"(b1));
}
__device__ __forceinline__ void mma_f16(float* d, uint32_t a0, uint32_t a1,
                                        uint32_t a2, uint32_t a3,
                                        uint32_t b0, uint32_t b1) {
    asm volatile("mma.sync.aligned.m16n8k16.row.col.f32.f16.f16.f32 "
        "{%0,%1,%2,%3},{%4,%5,%6,%7},{%8,%9},{%0,%1,%2,%3};"
        : "+f"(d[0]), "+f"(d[1]), "+f"(d[2]), "+f"(d[3])
        : "r"(a0), "r"(a1), "r"(a2), "r"(a3), "r"(b0), "r"(b1));
}
__device__ __forceinline__ void ldsm_x4_trans(uint32_t& r0, uint32_t& r1,
                                              uint32_t& r2, uint32_t& r3, uint32_t addr) {
    asm volatile("ldmatrix.sync.aligned.m8n8.x4.trans.shared.b16 {%0,%1,%2,%3}, [%4];"
        : "=r"(r0), "=r"(r1), "=r"(r2), "=r"(r3) : "r"(addr));
}

// ================= fp16 big-layer GEMM (double-buffered, 1 sync/chunk) =========
template<int COUT, bool XFORM, bool STATS, bool POOL>
__global__ void __launch_bounds__(256, (COUT == 64) ? 3 : 2)
gemm_h(const float* __restrict__ A, int lda,
       const __half* __restrict__ X,
       __half* __restrict__ Y,
       const float* __restrict__ bias,
       const double* __restrict__ bssum, const double* __restrict__ bssq,
       const float* __restrict__ bg, const float* __restrict__ bbe, int Cbn,
       double* __restrict__ ssum, double* __restrict__ ssq,
       float* __restrict__ pmax, float* __restrict__ pmin,
       int Cin)
{
    constexpr int MW = COUT / 4;
    constexpr int MF = MW / 16;
    constexpr int NH2 = COUT / 16;
    constexpr int XTILE = 32*128;
    constexpr int WTILE = COUT*40;
    extern __shared__ char xsm[];
    __half* sXh = (__half*)xsm;
    __half* sWh = sXh + 2*XTILE;
    __shared__ float tf_s[132], tf_h[132], tf_l[132];

    int p0 = blockIdx.x * 128;
    int tid = threadIdx.x;
    int lane = tid & 31, wid = tid >> 5;
    int warpM = wid >> 1, warpN = wid & 1;
    int gid = lane >> 2, tig = lane & 3;

    if (XFORM) {
        for (int c = tid; c < Cin; c += 256) {
            if (c < Cbn) {
                double m = bssum[c] / (double)P_TOT;
                double v = bssq[c] / (double)P_TOT - m*m;
                float sc = bg[c] * rsqrtf((float)v + EPSF);
                tf_s[c] = sc;
                tf_h[c] = bbe[c] - (float)m * sc;
                tf_l[c] = 0.f;
            } else {
                tf_s[c] = 1.f;
                tf_h[c] = 0.f;
                tf_l[c] = -3.4e38f;
            }
        }
    }

    uint32_t sX_base0 = (uint32_t)__cvta_generic_to_shared(sXh);

    float d[MF][8][4];
    #pragma unroll
    for (int mf = 0; mf < MF; ++mf)
        #pragma unroll
        for (int nf = 0; nf < 8; ++nf)
            #pragma unroll
            for (int i = 0; i < 4; ++i) d[mf][nf][i] = 0.f;

    uint4 xr[2];
    float wsf[2*NH2];
    int nchunk = (Cin + 31) >> 5;

    auto loadXreg = [&](int k0c) {
        #pragma unroll
        for (int j = 0; j < 2; ++j) {
            int id = tid + j*256;
            int k = id >> 4, seg = id & 15;
            int kg = k0c + k;
            uint4 v = make_uint4(0u, 0u, 0u, 0u);
            if (kg < Cin)
                v = *reinterpret_cast<const uint4*>(&X[(long)kg*P_TOT + p0 + seg*8]);
            xr[j] = v;
        }
    };
    auto storeX = [&](int k0c, int buf) {
        __half* dst = sXh + buf*XTILE;
        #pragma unroll
        for (int j = 0; j < 2; ++j) {
            int id = tid + j*256;
            int k = id >> 4, seg = id & 15;
            uint4 v = xr[j];
            if (XFORM) {
                int kg = k0c + k;
                if (kg < Cin) {
                    float s = tf_s[kg], h = tf_h[kg], l = tf_l[kg];
                    uint32_t* w = &v.x;
                    #pragma unroll
                    for (int q = 0; q < 4; ++q) {
                        __half2 hv = *reinterpret_cast<__half2*>(&w[q]);
                        float f0 = __low2float(hv), f1 = __high2float(hv);
                        f0 = fmaxf(fmaf(f0, s, h), l);
                        f1 = fmaxf(fmaf(f1, s, h), l);
                        __half2 ho = __floats2half2_rn(f0, f1);
                        w[q] = *reinterpret_cast<uint32_t*>(&ho);
                    }
                }
            }
            int segp = seg ^ (k & 7);
            *reinterpret_cast<uint4*>(&dst[k*128 + segp*8]) = v;
        }
    };
    auto loadWreg = [&](int k0c) {
        #pragma unroll
        for (int j = 0; j < NH2; ++j) {
            int hid = tid + j*256;
            int co = hid >> 4, kp = hid & 15;
            int k = k0c + 2*kp;
            wsf[2*j]   = (k   < Cin) ? A[(long)co*lda + k]   : 0.f;
            wsf[2*j+1] = (k+1 < Cin) ? A[(long)co*lda + k+1] : 0.f;
        }
    };
    auto storeW = [&](int buf) {
        __half* dst = sWh + buf*WTILE;
        #pragma unroll
        for (int j = 0; j < NH2; ++j) {
            int hid = tid + j*256;
            int co = hid >> 4, kp = hid & 15;
            __half2 hp = __floats2half2_rn(wsf[2*j], wsf[2*j+1]);
            *reinterpret_cast<__half2*>(&dst[co*40 + 2*kp]) = hp;
        }
    };

    auto mmaPhase = [&](int buf) {
        const __half* sW = sWh + buf*WTILE;
        uint32_t sX_base = sX_base0 + (uint32_t)(buf*XTILE*2);
        int mi = lane >> 3, lr = lane & 7;
        #pragma unroll
        for (int g16 = 0; g16 < 32; g16 += 16) {
            uint32_t a[MF][4];
            #pragma unroll
            for (int mf = 0; mf < MF; ++mf) {
                int r = warpM*MW + mf*16 + gid;
                a[mf][0] = *reinterpret_cast<const uint32_t*>(&sW[r*40 + g16 + 2*tig]);
                a[mf][1] = *reinterpret_cast<const uint32_t*>(&sW[(r+8)*40 + g16 + 2*tig]);
                a[mf][2] = *reinterpret_cast<const uint32_t*>(&sW[r*40 + g16 + 2*tig + 8]);
                a[mf][3] = *reinterpret_cast<const uint32_t*>(&sW[(r+8)*40 + g16 + 2*tig + 8]);
            }
            int kl = g16 + ((mi & 1) << 3) + lr;
            #pragma unroll
            for (int np = 0; np < 4; ++np) {
                int seg = warpN*8 + np*2 + (mi >> 1);
                int segp = seg ^ (kl & 7);
                uint32_t addr = sX_base + (uint32_t)((kl*128 + segp*8) * 2);
                uint32_t b0, b1, b2, b3;
                ldsm_x4_trans(b0, b1, b2, b3, addr);
                #pragma unroll
                for (int mf = 0; mf < MF; ++mf) {
                    mma_f16(d[mf][2*np],   a[mf][0], a[mf][1], a[mf][2], a[mf][3], b0, b1);
                    mma_f16(d[mf][2*np+1], a[mf][0], a[mf][1], a[mf][2], a[mf][3], b2, b3);
                }
            }
        }
    };

    loadXreg(0);
    loadWreg(0);
    if (XFORM) __syncthreads();
    storeX(0, 0);
    storeW(0);
    __syncthreads();
    for (int c0 = 0; c0 < nchunk; ++c0) {
        int cur = c0 & 1;
        if (c0 + 1 < nchunk) { loadXreg((c0+1)*32); loadWreg((c0+1)*32); }
        mmaPhase(cur);
        if (c0 + 1 < nchunk) {
            storeX((c0+1)*32, 1 - cur);
            storeW(1 - cur);
            __syncthreads();
        }
    }

    // epilogue
    #pragma unroll
    for (int mf = 0; mf < MF; ++mf) {
        int r = warpM*MW + mf*16 + gid;
        int co0 = r, co1 = r + 8;
        float bb0 = bias ? bias[co0] : 0.f;
        float bb1 = bias ? bias[co1] : 0.f;
        double s0 = 0.0, q0 = 0.0, s1 = 0.0, q1 = 0.0;
        float mxa[2], mna[2], mxb[2], mnb[2];
        if (POOL) {
            mxa[0] = mxa[1] = mxb[0] = mxb[1] = -3.4e38f;
            mna[0] = mna[1] = mnb[0] = mnb[1] =  3.4e38f;
        }
        #pragma unroll
        for (int nf = 0; nf < 8; ++nf) {
            int p = p0 + warpN*64 + nf*8 + 2*tig;
            float o0 = d[mf][nf][0] + bb0, o1 = d[mf][nf][1] + bb0;
            float o2 = d[mf][nf][2] + bb1, o3 = d[mf][nf][3] + bb1;
            if (!POOL) {
                *reinterpret_cast<__half2*>(&Y[(long)co0*P_TOT + p]) = __floats2half2_rn(o0, o1);
                *reinterpret_cast<__half2*>(&Y[(long)co1*P_TOT + p]) = __floats2half2_rn(o2, o3);
            } else {
                int g = nf >> 2;
                mxa[g] = fmaxf(mxa[g], fmaxf(o0, o1));
                mna[g] = fminf(mna[g], fminf(o0, o1));
                mxb[g] = fmaxf(mxb[g], fmaxf(o2, o3));
                mnb[g] = fminf(mnb[g], fminf(o2, o3));
            }
            if (STATS) {
                s0 += (double)o0 + (double)o1;
                q0 += (double)o0*o0 + (double)o1*o1;
                s1 += (double)o2 + (double)o3;
                q1 += (double)o2*o2 + (double)o3*o3;
            }
        }
        if (POOL) {
            const int PS = P_TOT >> 5;
            #pragma unroll
            for (int g = 0; g < 2; ++g) {
                float ma = mxa[g], na = mna[g], mb = mxb[g], nb = mnb[g];
                #pragma unroll
                for (int off = 1; off <= 2; off <<= 1) {
                    ma = fmaxf(ma, __shfl_xor_sync(0xFFFFFFFFu, ma, off));
                    na = fminf(na, __shfl_xor_sync(0xFFFFFFFFu, na, off));
                    mb = fmaxf(mb, __shfl_xor_sync(0xFFFFFFFFu, mb, off));
                    nb = fminf(nb, __shfl_xor_sync(0xFFFFFFFFu, nb, off));
                }
                if (tig == 0) {
                    int ps = (p0 >> 5) + warpN*2 + g;
                    pmax[(long)co0*PS + ps] = ma;
                    pmin[(long)co0*PS + ps] = na;
                    pmax[(long)co1*PS + ps] = mb;
                    pmin[(long)co1*PS + ps] = nb;
                }
            }
        }
        if (STATS) {
            #pragma unroll
            for (int off = 1; off <= 2; off <<= 1) {
                s0 += __shfl_xor_sync(0xFFFFFFFFu, s0, off);
                q0 += __shfl_xor_sync(0xFFFFFFFFu, q0, off);
                s1 += __shfl_xor_sync(0xFFFFFFFFu, s1, off);
                q1 += __shfl_xor_sync(0xFFFFFFFFu, q1, off);
            }
            if (tig == 0) {
                atomicAdd(&ssum[co0], s0);
                atomicAdd(&ssq[co0], q0);
                atomicAdd(&ssum[co1], s1);
                atomicAdd(&ssq[co1], q1);
            }
        }
    }
}

// ================= fp32/tf32 GEMM (attention; single-buffer) =================
// PSCALE: per-column scale = 1/(1e-9 + pscale[p]) precomputed per block in smem.
template<int COUT, bool TRANSA, bool SUB, bool PSCALE, bool STATS>
__global__ void __launch_bounds__(256)
gemm_tc(const float* __restrict__ A, int lda, long aStride,
        const float* __restrict__ X, const float* __restrict__ X2, long xStride,
        const float* __restrict__ pscale, int psStride,
        float* __restrict__ Y, long yStride,
        const float* __restrict__ bias,
        double* __restrict__ ssum, double* __restrict__ ssq,
        int Cin, int P)
{
    constexpr int MW = COUT / 4;
    constexpr int MF = MW / 16;
    constexpr int NW = (COUT*32)/256;
    extern __shared__ char xsm[];
    uint32_t* sX = (uint32_t*)xsm;              // 32*136
    uint32_t* sW = sX + 32*136;                 // COUT*36
    __shared__ float spsc[128];

    int by = blockIdx.y;
    A += (long)by * aStride;
    X += (long)by * xStride;
    if (SUB) X2 += (long)by * xStride;
    Y += (long)by * yStride;
    int coBase = blockIdx.z * COUT;
    int p0 = blockIdx.x * 128;

    int tid = threadIdx.x;
    int lane = tid & 31, wid = tid >> 5;
    int warpM = wid >> 1, warpN = wid & 1;
    int gid = lane >> 2, tig = lane & 3;

    if (PSCALE) {
        if (tid < 128)
            spsc[tid] = 1.f / (1e-9f + pscale[(long)by*psStride + p0 + tid]);
    }

    float d[MF][8][4];
    #pragma unroll
    for (int mf = 0; mf < MF; ++mf)
        #pragma unroll
        for (int nf = 0; nf < 8; ++nf)
            #pragma unroll
            for (int i = 0; i < 4; ++i) d[mf][nf][i] = 0.f;

    uint32_t xs[16];
    uint32_t ws[NW];
    int nchunk = (Cin + 31) >> 5;

    auto loadX_g = [&](int k0) {
        #pragma unroll
        for (int j = 0; j < 4; ++j) {
            int id = tid + j*256;
            int row = id >> 5, c4 = id & 31;
            int k = k0 + row;
            float4 v = make_float4(0.f, 0.f, 0.f, 0.f);
            if (k < Cin) {
                v = *reinterpret_cast<const float4*>(&X[(long)k*P + p0 + c4*4]);
                if (SUB) {
                    float4 u = *reinterpret_cast<const float4*>(&X2[(long)k*P + p0 + c4*4]);
                    v.x -= u.x; v.y -= u.y; v.z -= u.z; v.w -= u.w;
                }
                if (PSCALE) {
                    v.x *= spsc[c4*4+0]; v.y *= spsc[c4*4+1];
                    v.z *= spsc[c4*4+2]; v.w *= spsc[c4*4+3];
                }
            }
            xs[j*4+0] = f2tf32(v.x); xs[j*4+1] = f2tf32(v.y);
            xs[j*4+2] = f2tf32(v.z); xs[j*4+3] = f2tf32(v.w);
        }
    };
    auto loadW = [&](int k0) {
        #pragma unroll
        for (int j = 0; j < NW; ++j) {
            int id = tid + j*256;
            int co = id >> 5, kk = id & 31;
            int k = k0 + kk;
            float w = 0.f;
            if (k < Cin)
                w = TRANSA ? A[(long)k*lda + coBase + co]
                           : A[(long)(coBase + co)*lda + k];
            ws[j] = f2tf32(w);
        }
    };
    auto storeTiles = [&]() {
        #pragma unroll
        for (int j = 0; j < 4; ++j) {
            int id = tid + j*256;
            int row = id >> 5, c4 = id & 31;
            *reinterpret_cast<uint4*>(sX + row*136 + c4*4) =
                make_uint4(xs[j*4], xs[j*4+1], xs[j*4+2], xs[j*4+3]);
        }
        #pragma unroll
        for (int j = 0; j < NW; ++j) {
            int id = tid + j*256;
            int co = id >> 5, kk = id & 31;
            sW[co*36 + kk] = ws[j];
        }
    };
    auto mmaPhase = [&]() {
        #pragma unroll
        for (int k8 = 0; k8 < 4; ++k8) {
            int kb = k8*8;
            uint32_t a[MF][4];
            #pragma unroll
            for (int mf = 0; mf < MF; ++mf) {
                int r = warpM*MW + mf*16 + gid;
                a[mf][0] = sW[r*36 + kb + tig];
                a[mf][1] = sW[(r+8)*36 + kb + tig];
                a[mf][2] = sW[r*36 + kb + tig + 4];
                a[mf][3] = sW[(r+8)*36 + kb + tig + 4];
            }
            #pragma unroll
            for (int nf = 0; nf < 8; ++nf) {
                int col = warpN*64 + nf*8 + gid;
                uint32_t b0 = sX[(kb + tig)*136 + col];
                uint32_t b1 = sX[(kb + tig + 4)*136 + col];
                #pragma unroll
                for (int mf = 0; mf < MF; ++mf)
                    mma_tf32(d[mf][nf], a[mf][0], a[mf][1], a[mf][2], a[mf][3], b0, b1);
            }
        }
    };

    if (PSCALE) __syncthreads();        // spsc visible before loadX_g
    loadX_g(0);
    loadW(0);
    for (int c0 = 0; c0 < nchunk; ++c0) {
        storeTiles();
        __syncthreads();
        if (c0 + 1 < nchunk) { loadX_g((c0+1)*32); loadW((c0+1)*32); }
        mmaPhase();
        __syncthreads();
    }

    #pragma unroll
    for (int mf = 0; mf < MF; ++mf) {
        int r = warpM*MW + mf*16 + gid;
        int co0 = coBase + r, co1 = co0 + 8;
        float bb0 = bias ? bias[co0] : 0.f;
        float bb1 = bias ? bias[co1] : 0.f;
        double s0 = 0.0, q0 = 0.0, s1 = 0.0, q1 = 0.0;
        #pragma unroll
        for (int nf = 0; nf < 8; ++nf) {
            int p = p0 + warpN*64 + nf*8 + 2*tig;
            float o0 = d[mf][nf][0] + bb0, o1 = d[mf][nf][1] + bb0;
            float o2 = d[mf][nf][2] + bb1, o3 = d[mf][nf][3] + bb1;
            *reinterpret_cast<float2*>(&Y[(long)co0*P + p]) = make_float2(o0, o1);
            *reinterpret_cast<float2*>(&Y[(long)co1*P + p]) = make_float2(o2, o3);
            if (STATS) {
                s0 += (double)o0 + (double)o1;
                q0 += (double)o0*o0 + (double)o1*o1;
                s1 += (double)o2 + (double)o3;
                q1 += (double)o2*o2 + (double)o3*o3;
            }
        }
        if (STATS) {
            #pragma unroll
            for (int off = 1; off <= 2; off <<= 1) {
                s0 += __shfl_xor_sync(0xFFFFFFFFu, s0, off);
                q0 += __shfl_xor_sync(0xFFFFFFFFu, q0, off);
                s1 += __shfl_xor_sync(0xFFFFFFFFu, s1, off);
                q1 += __shfl_xor_sync(0xFFFFFFFFu, q1, off);
            }
            if (tig == 0) {
                atomicAdd(&ssum[co0], s0);
                atomicAdd(&ssq[co0], q0);
                atomicAdd(&ssum[co1], s1);
                atomicAdd(&ssq[co1], q1);
            }
        }
    }
}

// ---------------- pooled BN+ReLU finalize (also zeroes colsum buffer) ----------------
__global__ void __launch_bounds__(256) pool_finalize(float* __restrict__ xp,
                              const float* __restrict__ pmax, const float* __restrict__ pmin,
                              const double* __restrict__ bssum, const double* __restrict__ bssq,
                              const float* __restrict__ bg, const float* __restrict__ bbe,
                              float* __restrict__ colsum) {
    __shared__ float tf_s[128], tf_h[128];
    int tid = threadIdx.x;
    if (tid < 128) {
        double m = bssum[tid] / (double)P_TOT;
        double v = bssq[tid] / (double)P_TOT - m*m;
        float sc = bg[tid] * rsqrtf((float)v + EPSF);
        tf_s[tid] = sc;
        tf_h[tid] = bbe[tid] - (float)m * sc;
    }
    __syncthreads();
    int i = blockIdx.x*256 + tid;
    if (i < BB*NPT) colsum[i] = 0.f;
    if (i >= BB*128*NPT) return;
    int s = i & 511, c = (i >> 9) & 127, b = i >> 16;
    int src = c*(BB*NPT) + b*NPT + s;
    float sc = tf_s[c], sh = tf_h[c];
    float v = (sc >= 0.f) ? pmax[src] : pmin[src];
    xp[i] = fmaxf(fmaf(v, sc, sh), 0.f);
}

// ---------------- softmax rows (fast exp, fused column-sum atomics) ----------------
__global__ void __launch_bounds__(256) softmax_kernel(float* __restrict__ e,
                                                      float* __restrict__ colsum) {
    __shared__ float scol[NPT];
    int tid = threadIdx.x;
    int gw = (blockIdx.x*256 + tid) >> 5;
    int lane = tid & 31;
    scol[tid] = 0.f;
    scol[tid + 256] = 0.f;
    __syncthreads();
    float* row = e + (long)gw * NPT;
    float v[16];
    float mx = -3.4e38f;
    #pragma unroll
    for (int i = 0; i < 16; ++i) { v[i] = row[lane + i*32]; mx = fmaxf(mx, v[i]); }
    #pragma unroll
    for (int off = 16; off > 0; off >>= 1)
        mx = fmaxf(mx, __shfl_xor_sync(0xFFFFFFFFu, mx, off));
    float sum = 0.f;
    #pragma unroll
    for (int i = 0; i < 16; ++i) { v[i] = __expf(v[i] - mx); sum += v[i]; }
    #pragma unroll
    for (int off = 16; off > 0; off >>= 1)
        sum += __shfl_xor_sync(0xFFFFFFFFu, sum, off);
    float inv = 1.f / sum;
    #pragma unroll
    for (int i = 0; i < 16; ++i) {
        float r = v[i] * inv;
        row[lane + i*32] = r;
        atomicAdd(&scol[lane + i*32], r);
    }
    __syncthreads();
    int b = blockIdx.x >> 6;
    atomicAdd(&colsum[b*NPT + tid], scol[tid]);
    atomicAdd(&colsum[b*NPT + tid + 256], scol[tid + 256]);
}

// ---------------- final residual (inline bn1d affine) ----------------
__global__ void __launch_bounds__(256) final_kernel(float* __restrict__ out,
                             const float* __restrict__ xp,
                             const float* __restrict__ y,
                             const double* __restrict__ bssum, const double* __restrict__ bssq,
                             const float* __restrict__ bg, const float* __restrict__ bbe,
                             const float* __restrict__ alpha, const float* __restrict__ beta) {
    __shared__ float tf_s[128], tf_h[128];
    int tid = threadIdx.x;
    if (tid < 128) {
        double m = bssum[tid] / (double)(BB*NPT);
        double v = bssq[tid] / (double)(BB*NPT) - m*m;
        float sc = bg[tid] * rsqrtf((float)v + EPSF);
        tf_s[tid] = sc;
        tf_h[tid] = bbe[tid] - (float)m * sc;
    }
    __syncthreads();
    int i = blockIdx.x*256 + tid;
    if (i >= BB*128*NPT) return;
    int c = (i >> 9) & 127;
    float xr = fmaxf(fmaf(y[i], tf_s[c], tf_h[c]), 0.f);
    out[i] = xp[i] + alpha[c]*xr + beta[c];
}

// ---------------- launch ----------------
extern "C" void kernel_launch(void* const* d_in, const int* in_sizes, int n_in,
                              void* d_out, int out_size) {
    const float* xyz    = (const float*)d_in[0];
    const float* points = (const float*)d_in[1];
    const float* w0 = (const float*)d_in[2];
    const float* b0 = (const float*)d_in[3];
    const float* g0 = (const float*)d_in[4];
    const float* be0= (const float*)d_in[5];
    const float* w1 = (const float*)d_in[6];
    const float* b1 = (const float*)d_in[7];
    const float* g1 = (const float*)d_in[8];
    const float* be1= (const float*)d_in[9];
    const float* w2 = (const float*)d_in[10];
    const float* b2 = (const float*)d_in[11];
    const float* g2 = (const float*)d_in[12];
    const float* be2= (const float*)d_in[13];
    const float* wl = (const float*)d_in[14];
    const float* bl = (const float*)d_in[15];
    const float* gl = (const float*)d_in[16];
    const float* bel= (const float*)d_in[17];
    const float* wv = (const float*)d_in[18];
    const float* bv = (const float*)d_in[19];
    const float* wt = (const float*)d_in[20];
    const float* bt = (const float*)d_in[21];
    const float* gn = (const float*)d_in[22];
    const float* gb = (const float*)d_in[23];
    const float* alpha = (const float*)d_in[24];
    const float* beta  = (const float*)d_in[25];
    float* out = (float*)d_out;

    float *xp, *x0, *energy, *x2, *y, *colrcp, *pmax, *pmin, *ptsT;
    __half *hA, *hB;
    double *ssum, *ssq;
    int *fps, *nbr;
    cudaGetSymbolAddress((void**)&hA, g_hA);
    cudaGetSymbolAddress((void**)&hB, g_hB);
    cudaGetSymbolAddress((void**)&ptsT, g_ptsT);
    cudaGetSymbolAddress((void**)&xp, g_xp);
    cudaGetSymbolAddress((void**)&x0, g_x0);
    cudaGetSymbolAddress((void**)&energy, g_energy);
    cudaGetSymbolAddress((void**)&x2, g_x2);
    cudaGetSymbolAddress((void**)&y, g_y);
    cudaGetSymbolAddress((void**)&ssum, g_ssum);
    cudaGetSymbolAddress((void**)&ssq, g_ssq);
    cudaGetSymbolAddress((void**)&colrcp, g_colrcp);
    cudaGetSymbolAddress((void**)&pmax, g_pmax);
    cudaGetSymbolAddress((void**)&pmin, g_pmin);
    cudaGetSymbolAddress((void**)&fps, g_fps);
    cudaGetSymbolAddress((void**)&nbr, g_nbr);

    const int SMEM_PTS = 3*NN*sizeof(float);   // 48KB
    cudaFuncSetAttribute(fps_kernel,  cudaFuncAttributeMaxDynamicSharedMemorySize, 64*1024);
    cudaFuncSetAttribute(ball_kernel, cudaFuncAttributeMaxDynamicSharedMemorySize, 64*1024);

    const int SM_H64  = 2*(32*128 + 64*40) * 2;    // 26624
    const int SM_H128 = 2*(32*128 + 128*40) * 2;   // 36864
    const int SM_N128 = 32*136*4 + 128*36*4;       // 35840
    const int SM_N64  = 32*136*4 + 64*36*4;        // 26624

    // geometry
    transpose_pts<<<dim3(NN/64, BB), 256>>>(points, ptsT);
    fps_kernel<<<BB, 1024, SMEM_PTS>>>(xyz, fps);
    ball_kernel<<<dim3(NPT/16, BB), 512, SMEM_PTS>>>(xyz, fps, nbr);
    feat_kernel<<<dim3(NPT, BB), 256>>>(ptsT, xyz, fps, nbr, hB, hA + 128L*P_TOT);

    // L0: 128->64, stats slot0
    gemm_h<64,false,true,false><<<P_TOT/128, 256, SM_H64>>>(
        w0, 128, hB, hA, b0, nullptr, nullptr, nullptr, nullptr, 0,
        ssum+0, ssq+0, nullptr, nullptr, 128);
    newxyz_kernel<<<(BB*3*NPT + 255)/256, 256>>>(out, xyz, fps);

    // L1: 64->64, xform from slot0 stats (g0/be0), stats slot1
    gemm_h<64,true,true,false><<<P_TOT/128, 256, SM_H64>>>(
        w1, 64, hA, hB, b1, ssum+0, ssq+0, g0, be0, 64,
        ssum+128, ssq+128, nullptr, nullptr, 64);

    // L2: 64->128, xform from slot1 (g1/be1), stats slot2
    gemm_h<128,true,true,false><<<P_TOT/128, 256, SM_H128>>>(
        w2, 64, hB, hA, b2, ssum+128, ssq+128, g1, be1, 64,
        ssum+256, ssq+256, nullptr, nullptr, 64);

    // Ll: 131->128, xform from slot2 (g2/be2, 128 BN + 3 pass), stats slot3, POOL
    gemm_h<128,true,true,true><<<P_TOT/128, 256, SM_H128>>>(
        wl, 131, hA, nullptr, bl, ssum+256, ssq+256, g2, be2, 128,
        ssum+384, ssq+384, pmax, pmin, 131);
    pool_finalize<<<(BB*128*NPT + 255)/256, 256>>>(xp, pmax, pmin,
        ssum+384, ssq+384, gl, bel, colrcp);

    // attention (tf32); wv/x2/wt split into COUT=64 tiles for 2x parallelism
    gemm_tc<64,false,false,false,false><<<dim3(NPT/128, BB, 2), 256, SM_N64>>>(
        wv, 128, 0, xp, nullptr, PB, nullptr, 0, x0, PB, bv,
        nullptr, nullptr, 128, NPT);
    gemm_tc<128,true,false,false,false><<<dim3(NPT/128, BB, 4), 256, SM_N128>>>(
        xp, NPT, PB, x0, nullptr, PB, nullptr, 0, energy, (long)NPT*NPT, nullptr,
        nullptr, nullptr, 128, NPT);
    softmax_kernel<<<(BB*NPT)/8, 256>>>(energy, colrcp);
    // x2 = x0 @ attn (column renorm: reciprocal computed in-kernel from colsum)
    gemm_tc<64,false,false,true,false><<<dim3(NPT/128, BB, 2), 256, SM_N64>>>(
        x0, NPT, PB, energy, nullptr, (long)NPT*NPT, colrcp, NPT, x2, PB, nullptr,
        nullptr, nullptr, NPT, NPT);
    gemm_tc<64,false,true,false,true><<<dim3(NPT/128, BB, 2), 256, SM_N64>>>(
        wt, 128, 0, xp, x2, PB, nullptr, 0, y, PB, bt,
        ssum+512, ssq+512, 128, NPT);

    final_kernel<<<(BB*128*NPT + 255)/256, 256>>>(out + BB*3*NPT, xp, y,
        ssum+512, ssq+512, gn, gb, alpha, beta);
}